// round 13
// baseline (speedup 1.0000x reference)
#include <cuda_runtime.h>
#include <cuda_bf16.h>
#include <math.h>
#include <stdint.h>

#define BATCH 4
#define SEQ   1024
#define HID   1024
#define NH    16
#define HDIM  64

// ---------------------------------------------------------------------------
// Scratch (allocation-free rule: __device__ globals)
// ---------------------------------------------------------------------------
__device__ float g_Q[BATCH * SEQ * HID];
__device__ float g_K[BATCH * SEQ * HID];
__device__ float g_V[BATCH * SEQ * HID];
__device__ float g_A[BATCH * SEQ * HID];
// transposed + hi/lo-split weights: 4 x [N=1024][K=1024] bf16 (q,k,v,o)
__device__ __nv_bfloat16 g_W_hi[4][HID * HID];
__device__ __nv_bfloat16 g_W_lo[4][HID * HID];

// ---------------------------------------------------------------------------
// Helpers (plain sm_90-class PTX only: ldmatrix + mma.sync + cp.async)
// ---------------------------------------------------------------------------
__device__ __forceinline__ uint32_t smem_u32(const void* p) {
    return (uint32_t)__cvta_generic_to_shared(p);
}
__device__ __forceinline__ void ldsm4(uint32_t r[4], uint32_t addr) {
    asm volatile("ldmatrix.sync.aligned.m8n8.x4.shared.b16 {%0,%1,%2,%3}, [%4];"
                 : "=r"(r[0]), "=r"(r[1]), "=r"(r[2]), "=r"(r[3]) : "r"(addr));
}
__device__ __forceinline__ void ldsm4t(uint32_t r[4], uint32_t addr) {
    asm volatile("ldmatrix.sync.aligned.m8n8.x4.trans.shared.b16 {%0,%1,%2,%3}, [%4];"
                 : "=r"(r[0]), "=r"(r[1]), "=r"(r[2]), "=r"(r[3]) : "r"(addr));
}
__device__ __forceinline__ void mma_bf16(float c[4], const uint32_t a[4],
                                         uint32_t b0, uint32_t b1) {
    asm volatile(
        "mma.sync.aligned.m16n8k16.row.col.f32.bf16.bf16.f32 "
        "{%0,%1,%2,%3}, {%4,%5,%6,%7}, {%8,%9}, {%0,%1,%2,%3};"
        : "+f"(c[0]), "+f"(c[1]), "+f"(c[2]), "+f"(c[3])
        : "r"(a[0]), "r"(a[1]), "r"(a[2]), "r"(a[3]), "r"(b0), "r"(b1));
}
__device__ __forceinline__ void cp16(uint32_t s, const void* g) {
    asm volatile("cp.async.cg.shared.global [%0], [%1], 16;" :: "r"(s), "l"(g));
}
#define CP_COMMIT() asm volatile("cp.async.commit_group;")
#define CP_WAIT0()  asm volatile("cp.async.wait_group 0;")

// fp32x4 -> 4 bf16 hi (uint2) + 4 bf16 lo (uint2), lo = rn(x - hi)
__device__ __forceinline__ void split4(float4 x, uint2& hi, uint2& lo) {
    __nv_bfloat162 h0 = __floats2bfloat162_rn(x.x, x.y);
    __nv_bfloat162 h1 = __floats2bfloat162_rn(x.z, x.w);
    float2 f0 = __bfloat1622float2(h0);
    float2 f1 = __bfloat1622float2(h1);
    __nv_bfloat162 l0 = __floats2bfloat162_rn(x.x - f0.x, x.y - f0.y);
    __nv_bfloat162 l1 = __floats2bfloat162_rn(x.z - f1.x, x.w - f1.y);
    hi.x = *reinterpret_cast<uint32_t*>(&h0);
    hi.y = *reinterpret_cast<uint32_t*>(&h1);
    lo.x = *reinterpret_cast<uint32_t*>(&l0);
    lo.y = *reinterpret_cast<uint32_t*>(&l1);
}
__device__ __forceinline__ uint32_t pack2(float x, float y, uint32_t& lo) {
    __nv_bfloat162 h = __floats2bfloat162_rn(x, y);
    float2 f = __bfloat1622float2(h);
    __nv_bfloat162 l = __floats2bfloat162_rn(x - f.x, y - f.y);
    lo = *reinterpret_cast<uint32_t*>(&l);
    return *reinterpret_cast<uint32_t*>(&h);
}

// ---------------------------------------------------------------------------
// Weight prep (fused): W[K,N] fp32 -> WT_hi/WT_lo [N,K] bf16, all 4 weights
// ---------------------------------------------------------------------------
__global__ __launch_bounds__(256) void wprep4(
    const float* __restrict__ Wq, const float* __restrict__ Wk,
    const float* __restrict__ Wv, const float* __restrict__ Wo,
    __nv_bfloat16* __restrict__ WH, __nv_bfloat16* __restrict__ WL)
{
    __shared__ float t[32][33];
    const int z = blockIdx.z;
    const float* W = (z == 0) ? Wq : (z == 1) ? Wk : (z == 2) ? Wv : Wo;
    __nv_bfloat16* WT_hi = WH + (size_t)z * HID * HID;
    __nv_bfloat16* WT_lo = WL + (size_t)z * HID * HID;
    const int tx = threadIdx.x, ty = threadIdx.y;
    const int nb = blockIdx.x * 32, kb = blockIdx.y * 32;
    #pragma unroll
    for (int r = 0; r < 4; r++)
        t[ty + r * 8][tx] = W[(size_t)(kb + ty + r * 8) * HID + nb + tx];
    __syncthreads();
    #pragma unroll
    for (int r = 0; r < 4; r++) {
        const int n = nb + ty + r * 8;
        const int k = kb + tx;
        const float x = t[tx][ty + r * 8];
        __nv_bfloat16 h = __float2bfloat16(x);
        WT_hi[(size_t)n * HID + k] = h;
        WT_lo[(size_t)n * HID + k] = __float2bfloat16(x - __bfloat162float(h));
    }
}

// ---------------------------------------------------------------------------
// mma.sync bf16 GEMM, 3-term compensation, tile 128x256 (one wave: 128 CTAs).
// 256 threads = 8 warps (2m x 4n), warp tile 64x64. BK=32.
// B loaded via cp.async (already bf16); A register-staged + split.
// smem stage: Ahi(10240) | Alo(10240) | Bhi(20480) | Blo(20480) = 61440; x2.
// ---------------------------------------------------------------------------
#define AT 10240             // 128 rows * 80B
#define BT 20480             // 256 rows * 80B
#define STG 61440
#define G_SMEM (2 * STG)     // 122880

extern __shared__ char dyn_smem[];

__global__ __launch_bounds__(256) void gemm_mma(
    const float* __restrict__ A,
    const __nv_bfloat16* __restrict__ BhT,
    const __nv_bfloat16* __restrict__ BlT,
    const float* __restrict__ bias,
    float* __restrict__ C)
{
    char* smg = dyn_smem;
    const uint32_t sb = smem_u32(smg);
    const int tid = threadIdx.x;
    const int lane = tid & 31, wid = tid >> 5;
    const int wm = wid >> 2, wn = wid & 3;          // 2 x 4 warp grid
    const int bn = blockIdx.x, bm = blockIdx.y;

    const float* Ag = A + (size_t)bm * 128 * HID;
    const __nv_bfloat16* Bh = BhT + (size_t)bn * 256 * HID;
    const __nv_bfloat16* Bl = BlT + (size_t)bn * 256 * HID;

    float acc[4][8][4];
    #pragma unroll
    for (int i = 0; i < 4; i++)
        #pragma unroll
        for (int j = 0; j < 8; j++)
            #pragma unroll
            for (int r = 0; r < 4; r++) acc[i][j][r] = 0.0f;

    const int arow = tid >> 1, aq = tid & 1;        // A: 2 thr/row, 64B each
    const int brow4 = tid >> 2, bq = tid & 3;       // B: 4 thr/row, 16B each

    float4 aR[4];

    // ---- prologue: tile 0 ----
    {
        // B via cp.async
        const uint32_t s0 = sb + 2 * AT;
        #pragma unroll
        for (int i = 0; i < 4; i++) {
            const int row = brow4 + i * 64;
            const uint32_t sa = s0 + row * 80 + bq * 16;
            cp16(sa, (const char*)(Bh + (size_t)row * HID) + bq * 16);
            cp16(sa + BT, (const char*)(Bl + (size_t)row * HID) + bq * 16);
        }
        CP_COMMIT();
        // A regs -> split -> smem
        #pragma unroll
        for (int i = 0; i < 4; i++)
            aR[i] = *reinterpret_cast<const float4*>(
                Ag + (size_t)arow * HID + aq * 16 + i * 4);
        #pragma unroll
        for (int i = 0; i < 4; i++) {
            uint2 hi, lo;
            split4(aR[i], hi, lo);
            const int pos = aq * 4 + i;
            *reinterpret_cast<uint2*>(smg + arow * 80 + pos * 8) = hi;
            *reinterpret_cast<uint2*>(smg + AT + arow * 80 + pos * 8) = lo;
        }
        CP_WAIT0();
    }
    __syncthreads();

    const int r16 = lane & 15, hs = lane >> 4;
    const int NT = HID / 32;   // 32

    for (int t = 0; t < NT; t++) {
        const int buf = t & 1;
        // issue next tile's loads before compute
        if (t + 1 < NT) {
            const int kc = (t + 1) * 32;
            const uint32_t s0 = sb + (buf ^ 1) * STG + 2 * AT;
            #pragma unroll
            for (int i = 0; i < 4; i++) {
                const int row = brow4 + i * 64;
                const uint32_t sa = s0 + row * 80 + bq * 16;
                cp16(sa, (const char*)(Bh + (size_t)row * HID + kc) + bq * 16);
                cp16(sa + BT, (const char*)(Bl + (size_t)row * HID + kc) + bq * 16);
            }
            CP_COMMIT();
            #pragma unroll
            for (int i = 0; i < 4; i++)
                aR[i] = *reinterpret_cast<const float4*>(
                    Ag + (size_t)arow * HID + kc + aq * 16 + i * 4);
        }

        // ---- compute on smem[buf] ----
        const uint32_t s0 = sb + buf * STG;
        #pragma unroll
        for (int ks = 0; ks < 2; ks++) {
            const uint32_t koff = ks * 32 + hs * 16;
            uint32_t bhf[4][4], blf[4][4];
            #pragma unroll
            for (int p = 0; p < 4; p++) {
                const uint32_t bd =
                    s0 + 2 * AT + (wn * 64 + p * 16 + r16) * 80 + koff;
                ldsm4(bhf[p], bd);
                ldsm4(blf[p], bd + BT);
            }
            #pragma unroll
            for (int mt = 0; mt < 4; mt++) {
                uint32_t ah[4], al[4];
                const uint32_t ad = s0 + (wm * 64 + mt * 16 + r16) * 80 + koff;
                ldsm4(ah, ad);
                ldsm4(al, ad + AT);
                #pragma unroll
                for (int nt = 0; nt < 8; nt++) {
                    const int p = nt >> 1, s = nt & 1;
                    mma_bf16(acc[mt][nt], ah, bhf[p][s], bhf[p][s + 2]);
                    mma_bf16(acc[mt][nt], al, bhf[p][s], bhf[p][s + 2]);
                    mma_bf16(acc[mt][nt], ah, blf[p][s], blf[p][s + 2]);
                }
            }
        }

        // ---- store next A tile, wait B, sync ----
        if (t + 1 < NT) {
            char* st = smg + (buf ^ 1) * STG;
            #pragma unroll
            for (int i = 0; i < 4; i++) {
                uint2 hi, lo;
                split4(aR[i], hi, lo);
                const int pos = aq * 4 + i;
                *reinterpret_cast<uint2*>(st + arow * 80 + pos * 8) = hi;
                *reinterpret_cast<uint2*>(st + AT + arow * 80 + pos * 8) = lo;
            }
            CP_WAIT0();
            __syncthreads();
        }
    }

    // ---- epilogue: bias + store ----
    #pragma unroll
    for (int mt = 0; mt < 4; mt++) {
        const int row = bm * 128 + wm * 64 + mt * 16 + (lane >> 2);
        #pragma unroll
        for (int nt = 0; nt < 8; nt++) {
            const int col = bn * 256 + wn * 64 + nt * 8 + (lane & 3) * 2;
            const float2 bb = *reinterpret_cast<const float2*>(bias + col);
            float2 o0, o1;
            o0.x = acc[mt][nt][0] + bb.x;
            o0.y = acc[mt][nt][1] + bb.y;
            o1.x = acc[mt][nt][2] + bb.x;
            o1.y = acc[mt][nt][3] + bb.y;
            *reinterpret_cast<float2*>(C + (size_t)row * HID + col) = o0;
            *reinterpret_cast<float2*>(C + (size_t)(row + 8) * HID + col) = o1;
        }
    }
}

// ---------------------------------------------------------------------------
// Flash attention via mma.sync bf16 + 3-term compensation (R12, passing).
// ---------------------------------------------------------------------------
#define F_ROWB 144
#define F_TILE (128 * F_ROWB)      // 18432
#define F_SMEM (4 * F_TILE)        // 73728: Khi | Klo | Vhi | Vlo

__global__ __launch_bounds__(128, 2) void flash_mma(
    const float* __restrict__ Q, const float* __restrict__ K,
    const float* __restrict__ V, float* __restrict__ O)
{
    char* smg = dyn_smem;
    const uint32_t sb = smem_u32(smg);
    const int tid = threadIdx.x, lane = tid & 31, wid = tid >> 5;
    const int qt = blockIdx.x, h = blockIdx.y, b = blockIdx.z;
    const size_t qbase = (size_t)(b * SEQ + qt * 64);
    const size_t kbase = (size_t)(b * SEQ);
    const int colh = h * HDIM;

    // ---- prologue: stage scaled Q (64x64) hi/lo into K buffers ----
    {
        const int r0 = tid >> 4, q = tid & 15;
        #pragma unroll
        for (int p = 0; p < 8; p++) {
            const int row = r0 + p * 8;
            float4 x = *reinterpret_cast<const float4*>(
                Q + (qbase + row) * HID + colh + q * 4);
            x.x *= 0.03125f; x.y *= 0.03125f; x.z *= 0.03125f; x.w *= 0.03125f;
            uint2 hi, lo;
            split4(x, hi, lo);
            *reinterpret_cast<uint2*>(smg + row * F_ROWB + q * 8) = hi;
            *reinterpret_cast<uint2*>(smg + F_TILE + row * F_ROWB + q * 8) = lo;
        }
    }
    __syncthreads();
    uint32_t qh[4][4], ql[4][4];
    {
        const uint32_t base = sb + (wid * 16 + (lane & 15)) * F_ROWB + (lane >> 4) * 16;
        #pragma unroll
        for (int ks = 0; ks < 4; ks++) {
            ldsm4(qh[ks], base + ks * 32);
            ldsm4(ql[ks], base + ks * 32 + F_TILE);
        }
    }
    __syncthreads();

    float m0 = -1e30f, m1 = -1e30f, l0 = 0.0f, l1 = 0.0f;
    float oacc[8][4];
    #pragma unroll
    for (int j = 0; j < 8; j++)
        #pragma unroll
        for (int r = 0; r < 4; r++) oacc[j][r] = 0.0f;

    for (int kt = 0; kt < 8; kt++) {
        if (kt) __syncthreads();
        {
            const int r0 = tid >> 4, q = tid & 15;
            #pragma unroll
            for (int p = 0; p < 16; p++) {
                const int row = r0 + p * 8;
                const size_t g = (kbase + (size_t)kt * 128 + row) * HID + colh + q * 4;
                uint2 hi, lo;
                split4(*reinterpret_cast<const float4*>(K + g), hi, lo);
                *reinterpret_cast<uint2*>(smg + row * F_ROWB + q * 8) = hi;
                *reinterpret_cast<uint2*>(smg + F_TILE + row * F_ROWB + q * 8) = lo;
                split4(*reinterpret_cast<const float4*>(V + g), hi, lo);
                *reinterpret_cast<uint2*>(smg + 2 * F_TILE + row * F_ROWB + q * 8) = hi;
                *reinterpret_cast<uint2*>(smg + 3 * F_TILE + row * F_ROWB + q * 8) = lo;
            }
        }
        __syncthreads();

        float sacc[16][4];
        #pragma unroll
        for (int j = 0; j < 16; j++)
            #pragma unroll
            for (int r = 0; r < 4; r++) sacc[j][r] = 0.0f;

        #pragma unroll
        for (int ks = 0; ks < 4; ks++) {
            const uint32_t koff = ks * 32 + (lane >> 4) * 16;
            #pragma unroll
            for (int kg = 0; kg < 8; kg++) {
                uint32_t bh[4], bl[4];
                const uint32_t bd = sb + (kg * 16 + (lane & 15)) * F_ROWB + koff;
                ldsm4(bh, bd);
                ldsm4(bl, bd + F_TILE);
                mma_bf16(sacc[2 * kg],     qh[ks], bh[0], bh[2]);
                mma_bf16(sacc[2 * kg],     ql[ks], bh[0], bh[2]);
                mma_bf16(sacc[2 * kg],     qh[ks], bl[0], bl[2]);
                mma_bf16(sacc[2 * kg + 1], qh[ks], bh[1], bh[3]);
                mma_bf16(sacc[2 * kg + 1], ql[ks], bh[1], bh[3]);
                mma_bf16(sacc[2 * kg + 1], qh[ks], bl[1], bl[3]);
            }
        }

        float tm0 = -1e30f, tm1 = -1e30f;
        #pragma unroll
        for (int j = 0; j < 16; j++) {
            tm0 = fmaxf(tm0, fmaxf(sacc[j][0], sacc[j][1]));
            tm1 = fmaxf(tm1, fmaxf(sacc[j][2], sacc[j][3]));
        }
        tm0 = fmaxf(tm0, __shfl_xor_sync(0xffffffffu, tm0, 1));
        tm0 = fmaxf(tm0, __shfl_xor_sync(0xffffffffu, tm0, 2));
        tm1 = fmaxf(tm1, __shfl_xor_sync(0xffffffffu, tm1, 1));
        tm1 = fmaxf(tm1, __shfl_xor_sync(0xffffffffu, tm1, 2));
        const float nm0 = fmaxf(m0, tm0), nm1 = fmaxf(m1, tm1);
        const float a0 = __expf(m0 - nm0), a1 = __expf(m1 - nm1);
        float rs0 = 0.0f, rs1 = 0.0f;
        #pragma unroll
        for (int j = 0; j < 16; j++) {
            sacc[j][0] = __expf(sacc[j][0] - nm0);
            sacc[j][1] = __expf(sacc[j][1] - nm0);
            sacc[j][2] = __expf(sacc[j][2] - nm1);
            sacc[j][3] = __expf(sacc[j][3] - nm1);
            rs0 += sacc[j][0] + sacc[j][1];
            rs1 += sacc[j][2] + sacc[j][3];
        }
        rs0 += __shfl_xor_sync(0xffffffffu, rs0, 1);
        rs0 += __shfl_xor_sync(0xffffffffu, rs0, 2);
        rs1 += __shfl_xor_sync(0xffffffffu, rs1, 1);
        rs1 += __shfl_xor_sync(0xffffffffu, rs1, 2);
        l0 = l0 * a0 + rs0;
        l1 = l1 * a1 + rs1;
        m0 = nm0; m1 = nm1;
        #pragma unroll
        for (int j = 0; j < 8; j++) {
            oacc[j][0] *= a0; oacc[j][1] *= a0;
            oacc[j][2] *= a1; oacc[j][3] *= a1;
        }

        #pragma unroll
        for (int ks = 0; ks < 8; ks++) {
            uint32_t ah[4], al[4];
            ah[0] = pack2(sacc[2 * ks][0],     sacc[2 * ks][1],     al[0]);
            ah[1] = pack2(sacc[2 * ks][2],     sacc[2 * ks][3],     al[1]);
            ah[2] = pack2(sacc[2 * ks + 1][0], sacc[2 * ks + 1][1], al[2]);
            ah[3] = pack2(sacc[2 * ks + 1][2], sacc[2 * ks + 1][3], al[3]);
            const uint32_t vbase =
                sb + 2 * F_TILE + (ks * 16 + (lane & 15)) * F_ROWB + (lane >> 4) * 16;
            #pragma unroll
            for (int j = 0; j < 4; j++) {
                uint32_t vh[4], vl[4];
                ldsm4t(vh, vbase + j * 32);
                ldsm4t(vl, vbase + j * 32 + F_TILE);
                mma_bf16(oacc[2 * j],     ah, vh[0], vh[1]);
                mma_bf16(oacc[2 * j],     al, vh[0], vh[1]);
                mma_bf16(oacc[2 * j],     ah, vl[0], vl[1]);
                mma_bf16(oacc[2 * j + 1], ah, vh[2], vh[3]);
                mma_bf16(oacc[2 * j + 1], al, vh[2], vh[3]);
                mma_bf16(oacc[2 * j + 1], ah, vl[2], vl[3]);
            }
        }
    }

    const float il0 = 1.0f / l0, il1 = 1.0f / l1;
    const int r = lane >> 2;
    const size_t row0 = qbase + wid * 16 + r;
    #pragma unroll
    for (int j = 0; j < 8; j++) {
        const int col = colh + j * 8 + (lane & 3) * 2;
        float2 o0, o1;
        o0.x = oacc[j][0] * il0; o0.y = oacc[j][1] * il0;
        o1.x = oacc[j][2] * il1; o1.y = oacc[j][3] * il1;
        *reinterpret_cast<float2*>(O + row0 * HID + col) = o0;
        *reinterpret_cast<float2*>(O + (row0 + 8) * HID + col) = o1;
    }
}

// ---------------------------------------------------------------------------
extern "C" void kernel_launch(void* const* d_in, const int* in_sizes, int n_in,
                              void* d_out, int out_size)
{
    const float* vh = (const float*)d_in[0];
    const float* lh = (const float*)d_in[1];
    const float* qw = (const float*)d_in[2];
    const float* qb = (const float*)d_in[3];
    const float* kw = (const float*)d_in[4];
    const float* kb = (const float*)d_in[5];
    const float* vw = (const float*)d_in[6];
    const float* vb = (const float*)d_in[7];
    const float* ow = (const float*)d_in[8];
    const float* ob = (const float*)d_in[9];
    float* out = (float*)d_out;

    float *Qp, *Kp, *Vp, *Ap;
    cudaGetSymbolAddress((void**)&Qp, g_Q);
    cudaGetSymbolAddress((void**)&Kp, g_K);
    cudaGetSymbolAddress((void**)&Vp, g_V);
    cudaGetSymbolAddress((void**)&Ap, g_A);
    __nv_bfloat16 *WH, *WL;
    cudaGetSymbolAddress((void**)&WH, g_W_hi);
    cudaGetSymbolAddress((void**)&WL, g_W_lo);
    const size_t WSZ = (size_t)HID * HID;

    // weight prep (fused): transpose + bf16 hi/lo split, all 4 weights
    wprep4<<<dim3(HID / 32, HID / 32, 4), dim3(32, 8)>>>(qw, kw, vw, ow, WH, WL);

    cudaFuncSetAttribute(gemm_mma, cudaFuncAttributeMaxDynamicSharedMemorySize,
                         G_SMEM);
    dim3 ggrid(HID / 256, (BATCH * SEQ) / 128);  // (4, 32) = 128 CTAs = 1 wave

    gemm_mma<<<ggrid, 256, G_SMEM>>>(lh, WH + 0 * WSZ, WL + 0 * WSZ, qb, Qp);
    gemm_mma<<<ggrid, 256, G_SMEM>>>(vh, WH + 1 * WSZ, WL + 1 * WSZ, kb, Kp);
    gemm_mma<<<ggrid, 256, G_SMEM>>>(vh, WH + 2 * WSZ, WL + 2 * WSZ, vb, Vp);

    cudaFuncSetAttribute(flash_mma, cudaFuncAttributeMaxDynamicSharedMemorySize,
                         F_SMEM);
    flash_mma<<<dim3(SEQ / 64, NH, BATCH), 128, F_SMEM>>>(Qp, Kp, Vp, Ap);

    gemm_mma<<<ggrid, 256, G_SMEM>>>(Ap, WH + 3 * WSZ, WL + 3 * WSZ, ob, out);
}

// round 14
// speedup vs baseline: 1.0233x; 1.0233x over previous
#include <cuda_runtime.h>
#include <cuda_bf16.h>
#include <math.h>
#include <stdint.h>

#define BATCH 4
#define SEQ   1024
#define HID   1024
#define NH    16
#define HDIM  64
#define MTOT  (BATCH * SEQ)   // 4096

// ---------------------------------------------------------------------------
// Scratch (allocation-free rule: __device__ globals)
// ---------------------------------------------------------------------------
__device__ __nv_bfloat16 g_W_hi[4][HID * HID];
__device__ __nv_bfloat16 g_W_lo[4][HID * HID];
__device__ __nv_bfloat16 g_LHh[MTOT * HID], g_LHl[MTOT * HID];
__device__ __nv_bfloat16 g_VHh[MTOT * HID], g_VHl[MTOT * HID];
__device__ __nv_bfloat16 g_Qh[MTOT * HID],  g_Ql[MTOT * HID];
__device__ __nv_bfloat16 g_Kh[MTOT * HID],  g_Kl[MTOT * HID];
__device__ __nv_bfloat16 g_Vh[MTOT * HID],  g_Vl[MTOT * HID];
__device__ __nv_bfloat16 g_Ah[MTOT * HID],  g_Al[MTOT * HID];

// ---------------------------------------------------------------------------
// Helpers: ldmatrix + mma.sync + cp.async (plain targets only)
// ---------------------------------------------------------------------------
__device__ __forceinline__ uint32_t smem_u32(const void* p) {
    return (uint32_t)__cvta_generic_to_shared(p);
}
__device__ __forceinline__ void ldsm4(uint32_t r[4], uint32_t addr) {
    asm volatile("ldmatrix.sync.aligned.m8n8.x4.shared.b16 {%0,%1,%2,%3}, [%4];"
                 : "=r"(r[0]), "=r"(r[1]), "=r"(r[2]), "=r"(r[3]) : "r"(addr));
}
__device__ __forceinline__ void ldsm4t(uint32_t r[4], uint32_t addr) {
    asm volatile("ldmatrix.sync.aligned.m8n8.x4.trans.shared.b16 {%0,%1,%2,%3}, [%4];"
                 : "=r"(r[0]), "=r"(r[1]), "=r"(r[2]), "=r"(r[3]) : "r"(addr));
}
__device__ __forceinline__ void mma_bf16(float c[4], const uint32_t a[4],
                                         uint32_t b0, uint32_t b1) {
    asm volatile(
        "mma.sync.aligned.m16n8k16.row.col.f32.bf16.bf16.f32 "
        "{%0,%1,%2,%3}, {%4,%5,%6,%7}, {%8,%9}, {%0,%1,%2,%3};"
        : "+f"(c[0]), "+f"(c[1]), "+f"(c[2]), "+f"(c[3])
        : "r"(a[0]), "r"(a[1]), "r"(a[2]), "r"(a[3]), "r"(b0), "r"(b1));
}
__device__ __forceinline__ void cp16(uint32_t s, const void* g) {
    asm volatile("cp.async.cg.shared.global [%0], [%1], 16;" :: "r"(s), "l"(g));
}
#define CP_COMMIT() asm volatile("cp.async.commit_group;")
#define CP_WAIT0()  asm volatile("cp.async.wait_group 0;")
#define CP_WAIT1()  asm volatile("cp.async.wait_group 1;")

__device__ __forceinline__ void split4(float4 x, uint2& hi, uint2& lo) {
    __nv_bfloat162 h0 = __floats2bfloat162_rn(x.x, x.y);
    __nv_bfloat162 h1 = __floats2bfloat162_rn(x.z, x.w);
    float2 f0 = __bfloat1622float2(h0);
    float2 f1 = __bfloat1622float2(h1);
    __nv_bfloat162 l0 = __floats2bfloat162_rn(x.x - f0.x, x.y - f0.y);
    __nv_bfloat162 l1 = __floats2bfloat162_rn(x.z - f1.x, x.w - f1.y);
    hi.x = *reinterpret_cast<uint32_t*>(&h0);
    hi.y = *reinterpret_cast<uint32_t*>(&h1);
    lo.x = *reinterpret_cast<uint32_t*>(&l0);
    lo.y = *reinterpret_cast<uint32_t*>(&l1);
}
__device__ __forceinline__ uint32_t pack2(float x, float y, uint32_t& lo) {
    __nv_bfloat162 h = __floats2bfloat162_rn(x, y);
    float2 f = __bfloat1622float2(h);
    __nv_bfloat162 l = __floats2bfloat162_rn(x - f.x, y - f.y);
    lo = *reinterpret_cast<uint32_t*>(&l);
    return *reinterpret_cast<uint32_t*>(&h);
}

extern __shared__ char dyn_smem[];

// ---------------------------------------------------------------------------
// Weight prep (fused): W[K,N] fp32 -> WT_hi/WT_lo [N,K] bf16, all 4 weights
// ---------------------------------------------------------------------------
__global__ __launch_bounds__(256) void wprep4(
    const float* __restrict__ Wq, const float* __restrict__ Wk,
    const float* __restrict__ Wv, const float* __restrict__ Wo,
    __nv_bfloat16* __restrict__ WH, __nv_bfloat16* __restrict__ WL)
{
    __shared__ float t[32][33];
    const int z = blockIdx.z;
    const float* W = (z == 0) ? Wq : (z == 1) ? Wk : (z == 2) ? Wv : Wo;
    __nv_bfloat16* WT_hi = WH + (size_t)z * HID * HID;
    __nv_bfloat16* WT_lo = WL + (size_t)z * HID * HID;
    const int tx = threadIdx.x, ty = threadIdx.y;
    const int nb = blockIdx.x * 32, kb = blockIdx.y * 32;
    #pragma unroll
    for (int r = 0; r < 4; r++)
        t[ty + r * 8][tx] = W[(size_t)(kb + ty + r * 8) * HID + nb + tx];
    __syncthreads();
    #pragma unroll
    for (int r = 0; r < 4; r++) {
        const int n = nb + ty + r * 8;
        const int k = kb + tx;
        const float x = t[tx][ty + r * 8];
        __nv_bfloat16 h = __float2bfloat16(x);
        WT_hi[(size_t)n * HID + k] = h;
        WT_lo[(size_t)n * HID + k] = __float2bfloat16(x - __bfloat162float(h));
    }
}

// ---------------------------------------------------------------------------
// Activation prep: fp32 X -> hi/lo bf16 (elementwise). grid.z picks input.
// ---------------------------------------------------------------------------
__global__ __launch_bounds__(256) void aprep(
    const float* __restrict__ X0, const float* __restrict__ X1,
    __nv_bfloat16* __restrict__ H0, __nv_bfloat16* __restrict__ L0,
    __nv_bfloat16* __restrict__ H1, __nv_bfloat16* __restrict__ L1)
{
    const float* X = blockIdx.z ? X1 : X0;
    __nv_bfloat16* H = blockIdx.z ? H1 : H0;
    __nv_bfloat16* L = blockIdx.z ? L1 : L0;
    const size_t i = ((size_t)blockIdx.x * 256 + threadIdx.x) * 4;
    float4 x = *reinterpret_cast<const float4*>(X + i);
    uint2 hi, lo;
    split4(x, hi, lo);
    *reinterpret_cast<uint2*>(H + i) = hi;
    *reinterpret_cast<uint2*>(L + i) = lo;
}

// ---------------------------------------------------------------------------
// All-cp.async bf16 GEMM, 3-term compensation, tile 128x128, BK=32,
// 8 warps (2m x 4n), warp tile 64x32. 2 CTAs/SM (regs<=128, smem 80KB).
// A,B both pre-split hi/lo bf16 ([M][K] / [N][K]).
// Epilogue: fp32 C (Cf) OR hi/lo bf16 (Chi/Clo), value = (acc+bias)*scale.
// smem stage: Ahi|Alo|Bhi|Blo each 128*80B = 10240 -> stage 40960, x2.
// ---------------------------------------------------------------------------
#define AT2  10240
#define STG2 40960
#define G2_SMEM 81920

__global__ __launch_bounds__(256, 2) void gemm_mma(
    const __nv_bfloat16* __restrict__ Ah, const __nv_bfloat16* __restrict__ Al,
    const __nv_bfloat16* __restrict__ Bh, const __nv_bfloat16* __restrict__ Bl,
    const float* __restrict__ bias, float scale,
    float* __restrict__ Cf,
    __nv_bfloat16* __restrict__ Chi, __nv_bfloat16* __restrict__ Clo)
{
    char* smg = dyn_smem;
    const uint32_t sb = smem_u32(smg);
    const int tid = threadIdx.x;
    const int lane = tid & 31, wid = tid >> 5;
    const int wm = wid >> 2, wn = wid & 3;
    const int bn = blockIdx.x, bm = blockIdx.y;

    const __nv_bfloat16* Ahg = Ah + (size_t)bm * 128 * HID;
    const __nv_bfloat16* Alg = Al + (size_t)bm * 128 * HID;
    const __nv_bfloat16* Bhg = Bh + (size_t)bn * 128 * HID;
    const __nv_bfloat16* Blg = Bl + (size_t)bn * 128 * HID;

    float acc[4][4][4];
    #pragma unroll
    for (int i = 0; i < 4; i++)
        #pragma unroll
        for (int j = 0; j < 4; j++)
            #pragma unroll
            for (int r = 0; r < 4; r++) acc[i][j][r] = 0.0f;

    const int lrow = tid >> 2, lseg = tid & 3;   // 64 rows/pass, 16B segs

    // prologue: stage 0
    #pragma unroll
    for (int p = 0; p < 2; p++) {
        const int row = lrow + p * 64;
        const uint32_t sa = sb + row * 80 + lseg * 16;
        const size_t go = (size_t)row * HID;
        cp16(sa,           (const char*)(Ahg + go) + lseg * 16);
        cp16(sa + AT2,     (const char*)(Alg + go) + lseg * 16);
        cp16(sa + 2 * AT2, (const char*)(Bhg + go) + lseg * 16);
        cp16(sa + 3 * AT2, (const char*)(Blg + go) + lseg * 16);
    }
    CP_COMMIT();
    CP_WAIT0();
    __syncthreads();

    const int r16 = lane & 15, hs = lane >> 4;
    const int NT = HID / 32;   // 32

    for (int t = 0; t < NT; t++) {
        const int buf = t & 1;
        if (t + 1 < NT) {
            const int kc = (t + 1) * 32;
            const uint32_t s1 = sb + (buf ^ 1) * STG2;
            #pragma unroll
            for (int p = 0; p < 2; p++) {
                const int row = lrow + p * 64;
                const uint32_t sa = s1 + row * 80 + lseg * 16;
                const size_t go = (size_t)row * HID + kc;
                cp16(sa,           (const char*)(Ahg + go) + lseg * 16);
                cp16(sa + AT2,     (const char*)(Alg + go) + lseg * 16);
                cp16(sa + 2 * AT2, (const char*)(Bhg + go) + lseg * 16);
                cp16(sa + 3 * AT2, (const char*)(Blg + go) + lseg * 16);
            }
            CP_COMMIT();
        }

        const uint32_t s0 = sb + buf * STG2;
        #pragma unroll
        for (int ks = 0; ks < 2; ks++) {
            const uint32_t koff = ks * 32 + hs * 16;
            uint32_t bh[2][4], bl[2][4];
            #pragma unroll
            for (int p = 0; p < 2; p++) {
                const uint32_t bd =
                    s0 + 2 * AT2 + (wn * 32 + p * 16 + r16) * 80 + koff;
                ldsm4(bh[p], bd);
                ldsm4(bl[p], bd + AT2);
            }
            #pragma unroll
            for (int mt = 0; mt < 4; mt++) {
                uint32_t ah[4], al[4];
                const uint32_t ad = s0 + (wm * 64 + mt * 16 + r16) * 80 + koff;
                ldsm4(ah, ad);
                ldsm4(al, ad + AT2);
                #pragma unroll
                for (int nt = 0; nt < 4; nt++) {
                    const int p = nt >> 1, s = nt & 1;
                    mma_bf16(acc[mt][nt], ah, bh[p][s], bh[p][s + 2]);
                    mma_bf16(acc[mt][nt], al, bh[p][s], bh[p][s + 2]);
                    mma_bf16(acc[mt][nt], ah, bl[p][s], bl[p][s + 2]);
                }
            }
        }

        CP_WAIT0();
        __syncthreads();
    }

    // epilogue
    #pragma unroll
    for (int mt = 0; mt < 4; mt++) {
        const size_t grow = (size_t)(bm * 128 + wm * 64 + mt * 16 + (lane >> 2));
        #pragma unroll
        for (int nt = 0; nt < 4; nt++) {
            const int col = bn * 128 + wn * 32 + nt * 8 + (lane & 3) * 2;
            const float2 bb = *reinterpret_cast<const float2*>(bias + col);
            const float v0 = (acc[mt][nt][0] + bb.x) * scale;
            const float v1 = (acc[mt][nt][1] + bb.y) * scale;
            const float v2 = (acc[mt][nt][2] + bb.x) * scale;
            const float v3 = (acc[mt][nt][3] + bb.y) * scale;
            if (Cf) {
                float2 o0 = {v0, v1}, o1 = {v2, v3};
                *reinterpret_cast<float2*>(Cf + grow * HID + col) = o0;
                *reinterpret_cast<float2*>(Cf + (grow + 8) * HID + col) = o1;
            } else {
                uint32_t lo0, lo1;
                const uint32_t hi0 = pack2(v0, v1, lo0);
                const uint32_t hi1 = pack2(v2, v3, lo1);
                *reinterpret_cast<uint32_t*>(Chi + grow * HID + col) = hi0;
                *reinterpret_cast<uint32_t*>(Clo + grow * HID + col) = lo0;
                *reinterpret_cast<uint32_t*>(Chi + (grow + 8) * HID + col) = hi1;
                *reinterpret_cast<uint32_t*>(Clo + (grow + 8) * HID + col) = lo1;
            }
        }
    }
}

// ---------------------------------------------------------------------------
// Flash attention, all inputs pre-split hi/lo bf16, cp.async feeds,
// V-load overlapped with S-compute. Output written as hi/lo bf16.
// smem: Khi|Klo|Vhi|Vlo, each 128 rows x 144B = 18432 -> 73728 (2 CTAs/SM).
// Q staged through Khi/Klo region in prologue.
// ---------------------------------------------------------------------------
#define FR 144
#define FT 18432
#define F_SMEM (4 * FT)

__global__ __launch_bounds__(128, 2) void flash_mma(
    const __nv_bfloat16* __restrict__ Qh, const __nv_bfloat16* __restrict__ Ql,
    const __nv_bfloat16* __restrict__ Kh, const __nv_bfloat16* __restrict__ Kl,
    const __nv_bfloat16* __restrict__ Vh, const __nv_bfloat16* __restrict__ Vl,
    __nv_bfloat16* __restrict__ Ahi, __nv_bfloat16* __restrict__ Alo)
{
    char* smg = dyn_smem;
    const uint32_t sb = smem_u32(smg);
    const int tid = threadIdx.x, lane = tid & 31, wid = tid >> 5;
    const int qt = blockIdx.x, h = blockIdx.y, b = blockIdx.z;
    const size_t qbase = (size_t)(b * SEQ + qt * 64);
    const size_t kbase = (size_t)(b * SEQ);
    const int colh = h * HDIM;

    const int lr = tid >> 3;        // 0..15
    const int lseg = tid & 7;       // 16B segs over 128B rows

    // ---- prologue: Q hi/lo (64 x 64) via cp.async into K region ----
    #pragma unroll
    for (int p = 0; p < 4; p++) {
        const int row = lr + p * 16;
        const uint32_t sa = sb + row * FR + lseg * 16;
        const size_t go = (qbase + row) * HID + colh;
        cp16(sa,      (const char*)(Qh + go) + lseg * 16);
        cp16(sa + FT, (const char*)(Ql + go) + lseg * 16);
    }
    CP_COMMIT();
    CP_WAIT0();
    __syncthreads();

    uint32_t qh[4][4], ql[4][4];
    {
        const uint32_t base = sb + (wid * 16 + (lane & 15)) * FR + (lane >> 4) * 16;
        #pragma unroll
        for (int ks = 0; ks < 4; ks++) {
            ldsm4(qh[ks], base + ks * 32);
            ldsm4(ql[ks], base + ks * 32 + FT);
        }
    }
    __syncthreads();

    float m0 = -1e30f, m1 = -1e30f, l0 = 0.0f, l1 = 0.0f;
    float oacc[8][4];
    #pragma unroll
    for (int j = 0; j < 8; j++)
        #pragma unroll
        for (int r = 0; r < 4; r++) oacc[j][r] = 0.0f;

    for (int kt = 0; kt < 8; kt++) {
        // ---- K loads (group A), then V loads (group B) ----
        #pragma unroll
        for (int p = 0; p < 8; p++) {
            const int row = lr + p * 16;
            const uint32_t sa = sb + row * FR + lseg * 16;
            const size_t go = (kbase + (size_t)kt * 128 + row) * HID + colh;
            cp16(sa,      (const char*)(Kh + go) + lseg * 16);
            cp16(sa + FT, (const char*)(Kl + go) + lseg * 16);
        }
        CP_COMMIT();
        #pragma unroll
        for (int p = 0; p < 8; p++) {
            const int row = lr + p * 16;
            const uint32_t sa = sb + 2 * FT + row * FR + lseg * 16;
            const size_t go = (kbase + (size_t)kt * 128 + row) * HID + colh;
            cp16(sa,      (const char*)(Vh + go) + lseg * 16);
            cp16(sa + FT, (const char*)(Vl + go) + lseg * 16);
        }
        CP_COMMIT();

        CP_WAIT1();          // K ready; V still in flight
        __syncthreads();

        // ---- S = Q K^T ----
        float sacc[16][4];
        #pragma unroll
        for (int j = 0; j < 16; j++)
            #pragma unroll
            for (int r = 0; r < 4; r++) sacc[j][r] = 0.0f;

        #pragma unroll
        for (int ks = 0; ks < 4; ks++) {
            const uint32_t koff = ks * 32 + (lane >> 4) * 16;
            #pragma unroll
            for (int kg = 0; kg < 8; kg++) {
                uint32_t bh[4], bl[4];
                const uint32_t bd = sb + (kg * 16 + (lane & 15)) * FR + koff;
                ldsm4(bh, bd);
                ldsm4(bl, bd + FT);
                mma_bf16(sacc[2 * kg],     qh[ks], bh[0], bh[2]);
                mma_bf16(sacc[2 * kg],     ql[ks], bh[0], bh[2]);
                mma_bf16(sacc[2 * kg],     qh[ks], bl[0], bl[2]);
                mma_bf16(sacc[2 * kg + 1], qh[ks], bh[1], bh[3]);
                mma_bf16(sacc[2 * kg + 1], ql[ks], bh[1], bh[3]);
                mma_bf16(sacc[2 * kg + 1], qh[ks], bl[1], bl[3]);
            }
        }

        // ---- online softmax ----
        float tm0 = -1e30f, tm1 = -1e30f;
        #pragma unroll
        for (int j = 0; j < 16; j++) {
            tm0 = fmaxf(tm0, fmaxf(sacc[j][0], sacc[j][1]));
            tm1 = fmaxf(tm1, fmaxf(sacc[j][2], sacc[j][3]));
        }
        tm0 = fmaxf(tm0, __shfl_xor_sync(0xffffffffu, tm0, 1));
        tm0 = fmaxf(tm0, __shfl_xor_sync(0xffffffffu, tm0, 2));
        tm1 = fmaxf(tm1, __shfl_xor_sync(0xffffffffu, tm1, 1));
        tm1 = fmaxf(tm1, __shfl_xor_sync(0xffffffffu, tm1, 2));
        const float nm0 = fmaxf(m0, tm0), nm1 = fmaxf(m1, tm1);
        const float a0 = __expf(m0 - nm0), a1 = __expf(m1 - nm1);
        float rs0 = 0.0f, rs1 = 0.0f;
        #pragma unroll
        for (int j = 0; j < 16; j++) {
            sacc[j][0] = __expf(sacc[j][0] - nm0);
            sacc[j][1] = __expf(sacc[j][1] - nm0);
            sacc[j][2] = __expf(sacc[j][2] - nm1);
            sacc[j][3] = __expf(sacc[j][3] - nm1);
            rs0 += sacc[j][0] + sacc[j][1];
            rs1 += sacc[j][2] + sacc[j][3];
        }
        rs0 += __shfl_xor_sync(0xffffffffu, rs0, 1);
        rs0 += __shfl_xor_sync(0xffffffffu, rs0, 2);
        rs1 += __shfl_xor_sync(0xffffffffu, rs1, 1);
        rs1 += __shfl_xor_sync(0xffffffffu, rs1, 2);
        l0 = l0 * a0 + rs0;
        l1 = l1 * a1 + rs1;
        m0 = nm0; m1 = nm1;
        #pragma unroll
        for (int j = 0; j < 8; j++) {
            oacc[j][0] *= a0; oacc[j][1] *= a0;
            oacc[j][2] *= a1; oacc[j][3] *= a1;
        }

        CP_WAIT0();          // V ready
        __syncthreads();

        // ---- O += P V ----
        #pragma unroll
        for (int ks = 0; ks < 8; ks++) {
            uint32_t ah[4], al[4];
            ah[0] = pack2(sacc[2 * ks][0],     sacc[2 * ks][1],     al[0]);
            ah[1] = pack2(sacc[2 * ks][2],     sacc[2 * ks][3],     al[1]);
            ah[2] = pack2(sacc[2 * ks + 1][0], sacc[2 * ks + 1][1], al[2]);
            ah[3] = pack2(sacc[2 * ks + 1][2], sacc[2 * ks + 1][3], al[3]);
            const uint32_t vbase =
                sb + 2 * FT + (ks * 16 + (lane & 15)) * FR + (lane >> 4) * 16;
            #pragma unroll
            for (int j = 0; j < 4; j++) {
                uint32_t vh[4], vl[4];
                ldsm4t(vh, vbase + j * 32);
                ldsm4t(vl, vbase + j * 32 + FT);
                mma_bf16(oacc[2 * j],     ah, vh[0], vh[1]);
                mma_bf16(oacc[2 * j],     al, vh[0], vh[1]);
                mma_bf16(oacc[2 * j],     ah, vl[0], vl[1]);
                mma_bf16(oacc[2 * j + 1], ah, vh[2], vh[3]);
                mma_bf16(oacc[2 * j + 1], al, vh[2], vh[3]);
                mma_bf16(oacc[2 * j + 1], ah, vl[2], vl[3]);
            }
        }
        __syncthreads();     // release K/V buffers for next kt
    }

    // ---- epilogue: O/l -> hi/lo bf16 ----
    const float il0 = 1.0f / l0, il1 = 1.0f / l1;
    const size_t row0 = qbase + wid * 16 + (lane >> 2);
    #pragma unroll
    for (int j = 0; j < 8; j++) {
        const int col = colh + j * 8 + (lane & 3) * 2;
        uint32_t lo0, lo1;
        const uint32_t hi0 = pack2(oacc[j][0] * il0, oacc[j][1] * il0, lo0);
        const uint32_t hi1 = pack2(oacc[j][2] * il1, oacc[j][3] * il1, lo1);
        *reinterpret_cast<uint32_t*>(Ahi + row0 * HID + col) = hi0;
        *reinterpret_cast<uint32_t*>(Alo + row0 * HID + col) = lo0;
        *reinterpret_cast<uint32_t*>(Ahi + (row0 + 8) * HID + col) = hi1;
        *reinterpret_cast<uint32_t*>(Alo + (row0 + 8) * HID + col) = lo1;
    }
}

// ---------------------------------------------------------------------------
extern "C" void kernel_launch(void* const* d_in, const int* in_sizes, int n_in,
                              void* d_out, int out_size)
{
    const float* vh = (const float*)d_in[0];
    const float* lh = (const float*)d_in[1];
    const float* qw = (const float*)d_in[2];
    const float* qb = (const float*)d_in[3];
    const float* kw = (const float*)d_in[4];
    const float* kb = (const float*)d_in[5];
    const float* vw = (const float*)d_in[6];
    const float* vb = (const float*)d_in[7];
    const float* ow = (const float*)d_in[8];
    const float* ob = (const float*)d_in[9];
    float* out = (float*)d_out;

    __nv_bfloat16 *WH, *WL, *LHh, *LHl, *VHh, *VHl;
    __nv_bfloat16 *Qh, *Ql, *Kh, *Kl, *Vh, *Vl, *Ah, *Al;
    cudaGetSymbolAddress((void**)&WH,  g_W_hi);
    cudaGetSymbolAddress((void**)&WL,  g_W_lo);
    cudaGetSymbolAddress((void**)&LHh, g_LHh);
    cudaGetSymbolAddress((void**)&LHl, g_LHl);
    cudaGetSymbolAddress((void**)&VHh, g_VHh);
    cudaGetSymbolAddress((void**)&VHl, g_VHl);
    cudaGetSymbolAddress((void**)&Qh,  g_Qh);
    cudaGetSymbolAddress((void**)&Ql,  g_Ql);
    cudaGetSymbolAddress((void**)&Kh,  g_Kh);
    cudaGetSymbolAddress((void**)&Kl,  g_Kl);
    cudaGetSymbolAddress((void**)&Vh,  g_Vh);
    cudaGetSymbolAddress((void**)&Vl,  g_Vl);
    cudaGetSymbolAddress((void**)&Ah,  g_Ah);
    cudaGetSymbolAddress((void**)&Al,  g_Al);
    const size_t WSZ = (size_t)HID * HID;

    // preps
    wprep4<<<dim3(HID / 32, HID / 32, 4), dim3(32, 8)>>>(qw, kw, vw, ow, WH, WL);
    aprep<<<dim3(MTOT * HID / 1024, 1, 2), 256>>>(lh, vh, LHh, LHl, VHh, VHl);

    cudaFuncSetAttribute(gemm_mma, cudaFuncAttributeMaxDynamicSharedMemorySize,
                         G2_SMEM);
    cudaFuncSetAttribute(flash_mma, cudaFuncAttributeMaxDynamicSharedMemorySize,
                         F_SMEM);
    dim3 ggrid(HID / 128, MTOT / 128);   // (8, 32) = 256 CTAs, 2/SM -> 1 wave

    // QKV projections -> hi/lo bf16 (Q pre-scaled by 1/32)
    gemm_mma<<<ggrid, 256, G2_SMEM>>>(LHh, LHl, WH + 0 * WSZ, WL + 0 * WSZ,
                                      qb, 0.03125f, nullptr, Qh, Ql);
    gemm_mma<<<ggrid, 256, G2_SMEM>>>(VHh, VHl, WH + 1 * WSZ, WL + 1 * WSZ,
                                      kb, 1.0f, nullptr, Kh, Kl);
    gemm_mma<<<ggrid, 256, G2_SMEM>>>(VHh, VHl, WH + 2 * WSZ, WL + 2 * WSZ,
                                      vb, 1.0f, nullptr, Vh, Vl);

    // attention -> hi/lo bf16
    flash_mma<<<dim3(SEQ / 64, NH, BATCH), 128, F_SMEM>>>(Qh, Ql, Kh, Kl,
                                                          Vh, Vl, Ah, Al);

    // output projection -> fp32 d_out
    gemm_mma<<<ggrid, 256, G2_SMEM>>>(Ah, Al, WH + 3 * WSZ, WL + 3 * WSZ,
                                      ob, 1.0f, out, nullptr, nullptr);
}

// round 15
// speedup vs baseline: 1.0729x; 1.0485x over previous
#include <cuda_runtime.h>
#include <cuda_bf16.h>
#include <math.h>
#include <stdint.h>

#define BATCH 4
#define SEQ   1024
#define HID   1024
#define NH    16
#define HDIM  64
#define MTOT  (BATCH * SEQ)   // 4096

// ---------------------------------------------------------------------------
// Scratch (allocation-free rule: __device__ globals)
// ---------------------------------------------------------------------------
__device__ __nv_bfloat16 g_W_hi[4][HID * HID];
__device__ __nv_bfloat16 g_W_lo[4][HID * HID];
__device__ __nv_bfloat16 g_LHh[MTOT * HID], g_LHl[MTOT * HID];
__device__ __nv_bfloat16 g_VHh[MTOT * HID], g_VHl[MTOT * HID];
__device__ __nv_bfloat16 g_Qh[MTOT * HID],  g_Ql[MTOT * HID];
__device__ __nv_bfloat16 g_Kh[MTOT * HID],  g_Kl[MTOT * HID];
__device__ __nv_bfloat16 g_Vh[MTOT * HID],  g_Vl[MTOT * HID];
__device__ __nv_bfloat16 g_Ah[MTOT * HID],  g_Al[MTOT * HID];

// ---------------------------------------------------------------------------
// Helpers
// ---------------------------------------------------------------------------
__device__ __forceinline__ uint32_t smem_u32(const void* p) {
    return (uint32_t)__cvta_generic_to_shared(p);
}
__device__ __forceinline__ void ldsm4(uint32_t r[4], uint32_t addr) {
    asm volatile("ldmatrix.sync.aligned.m8n8.x4.shared.b16 {%0,%1,%2,%3}, [%4];"
                 : "=r"(r[0]), "=r"(r[1]), "=r"(r[2]), "=r"(r[3]) : "r"(addr));
}
__device__ __forceinline__ void ldsm4t(uint32_t r[4], uint32_t addr) {
    asm volatile("ldmatrix.sync.aligned.m8n8.x4.trans.shared.b16 {%0,%1,%2,%3}, [%4];"
                 : "=r"(r[0]), "=r"(r[1]), "=r"(r[2]), "=r"(r[3]) : "r"(addr));
}
__device__ __forceinline__ void mma_bf16(float c[4], const uint32_t a[4],
                                         uint32_t b0, uint32_t b1) {
    asm volatile(
        "mma.sync.aligned.m16n8k16.row.col.f32.bf16.bf16.f32 "
        "{%0,%1,%2,%3}, {%4,%5,%6,%7}, {%8,%9}, {%0,%1,%2,%3};"
        : "+f"(c[0]), "+f"(c[1]), "+f"(c[2]), "+f"(c[3])
        : "r"(a[0]), "r"(a[1]), "r"(a[2]), "r"(a[3]), "r"(b0), "r"(b1));
}
__device__ __forceinline__ void cp16(uint32_t s, const void* g) {
    asm volatile("cp.async.cg.shared.global [%0], [%1], 16;" :: "r"(s), "l"(g));
}
#define CP_COMMIT() asm volatile("cp.async.commit_group;")
#define CP_WAIT0()  asm volatile("cp.async.wait_group 0;")
#define CP_WAIT1()  asm volatile("cp.async.wait_group 1;")
#define CP_WAIT2()  asm volatile("cp.async.wait_group 2;")

__device__ __forceinline__ void split4(float4 x, uint2& hi, uint2& lo) {
    __nv_bfloat162 h0 = __floats2bfloat162_rn(x.x, x.y);
    __nv_bfloat162 h1 = __floats2bfloat162_rn(x.z, x.w);
    float2 f0 = __bfloat1622float2(h0);
    float2 f1 = __bfloat1622float2(h1);
    __nv_bfloat162 l0 = __floats2bfloat162_rn(x.x - f0.x, x.y - f0.y);
    __nv_bfloat162 l1 = __floats2bfloat162_rn(x.z - f1.x, x.w - f1.y);
    hi.x = *reinterpret_cast<uint32_t*>(&h0);
    hi.y = *reinterpret_cast<uint32_t*>(&h1);
    lo.x = *reinterpret_cast<uint32_t*>(&l0);
    lo.y = *reinterpret_cast<uint32_t*>(&l1);
}
__device__ __forceinline__ uint32_t pack2(float x, float y, uint32_t& lo) {
    __nv_bfloat162 h = __floats2bfloat162_rn(x, y);
    float2 f = __bfloat1622float2(h);
    __nv_bfloat162 l = __floats2bfloat162_rn(x - f.x, y - f.y);
    lo = *reinterpret_cast<uint32_t*>(&l);
    return *reinterpret_cast<uint32_t*>(&h);
}

extern __shared__ char dyn_smem[];

// ---------------------------------------------------------------------------
// Weight prep (fused): W[K,N] fp32 -> WT_hi/WT_lo [N,K] bf16, all 4 weights
// ---------------------------------------------------------------------------
__global__ __launch_bounds__(256) void wprep4(
    const float* __restrict__ Wq, const float* __restrict__ Wk,
    const float* __restrict__ Wv, const float* __restrict__ Wo,
    __nv_bfloat16* __restrict__ WH, __nv_bfloat16* __restrict__ WL)
{
    __shared__ float t[32][33];
    const int z = blockIdx.z;
    const float* W = (z == 0) ? Wq : (z == 1) ? Wk : (z == 2) ? Wv : Wo;
    __nv_bfloat16* WT_hi = WH + (size_t)z * HID * HID;
    __nv_bfloat16* WT_lo = WL + (size_t)z * HID * HID;
    const int tx = threadIdx.x, ty = threadIdx.y;
    const int nb = blockIdx.x * 32, kb = blockIdx.y * 32;
    #pragma unroll
    for (int r = 0; r < 4; r++)
        t[ty + r * 8][tx] = W[(size_t)(kb + ty + r * 8) * HID + nb + tx];
    __syncthreads();
    #pragma unroll
    for (int r = 0; r < 4; r++) {
        const int n = nb + ty + r * 8;
        const int k = kb + tx;
        const float x = t[tx][ty + r * 8];
        __nv_bfloat16 h = __float2bfloat16(x);
        WT_hi[(size_t)n * HID + k] = h;
        WT_lo[(size_t)n * HID + k] = __float2bfloat16(x - __bfloat162float(h));
    }
}

// ---------------------------------------------------------------------------
// Activation prep: fp32 X -> hi/lo bf16 (elementwise). grid.z picks input.
// ---------------------------------------------------------------------------
__global__ __launch_bounds__(256) void aprep(
    const float* __restrict__ X0, const float* __restrict__ X1,
    __nv_bfloat16* __restrict__ H0, __nv_bfloat16* __restrict__ L0,
    __nv_bfloat16* __restrict__ H1, __nv_bfloat16* __restrict__ L1)
{
    const float* X = blockIdx.z ? X1 : X0;
    __nv_bfloat16* H = blockIdx.z ? H1 : H0;
    __nv_bfloat16* L = blockIdx.z ? L1 : L0;
    const size_t i = ((size_t)blockIdx.x * 256 + threadIdx.x) * 4;
    float4 x = *reinterpret_cast<const float4*>(X + i);
    uint2 hi, lo;
    split4(x, hi, lo);
    *reinterpret_cast<uint2*>(H + i) = hi;
    *reinterpret_cast<uint2*>(L + i) = lo;
}

// ---------------------------------------------------------------------------
// Deep-pipelined bf16 GEMM core: tile 128x128, BK=16, 4 cp.async stages
// (3 in flight), 8 warps (2m x 4n), warp tile 64x32, 2 CTAs/SM.
// smem stage: Ahi|Alo|Bhi|Blo, each 128 rows x 48B = 6144 -> 24576; x4 stages.
// 48B row stride is ldmatrix conflict-free (bank pattern all-distinct).
// ---------------------------------------------------------------------------
#define AT3   6144
#define STG3  24576
#define G3_SMEM (4 * STG3)   // 98304

// core loop shared by both GEMM kernels
#define GEMM_CORE(Ahg, Alg, Bhg, Blg)                                          \
    float acc[4][4][4];                                                        \
    _Pragma("unroll") for (int i = 0; i < 4; i++)                              \
        _Pragma("unroll") for (int j = 0; j < 4; j++)                          \
            _Pragma("unroll") for (int r = 0; r < 4; r++) acc[i][j][r] = 0.0f; \
    const int lrow = tid >> 1, lseg = tid & 1;                                 \
    const char* gA_h = (const char*)((Ahg) + (size_t)lrow * HID) + lseg * 16;  \
    const char* gA_l = (const char*)((Alg) + (size_t)lrow * HID) + lseg * 16;  \
    const char* gB_h = (const char*)((Bhg) + (size_t)lrow * HID) + lseg * 16;  \
    const char* gB_l = (const char*)((Blg) + (size_t)lrow * HID) + lseg * 16;  \
    const uint32_t swr = lrow * 48 + lseg * 16;                                \
    _Pragma("unroll") for (int s = 0; s < 3; s++) {                            \
        const uint32_t sa = sb + s * STG3 + swr;                               \
        cp16(sa,           gA_h + s * 32);                                     \
        cp16(sa + AT3,     gA_l + s * 32);                                     \
        cp16(sa + 2 * AT3, gB_h + s * 32);                                     \
        cp16(sa + 3 * AT3, gB_l + s * 32);                                     \
        CP_COMMIT();                                                           \
    }                                                                          \
    const int r16 = lane & 15;                                                 \
    const uint32_t koff = (lane >> 4) * 16;                                    \
    const uint32_t aoff = (wm * 64 + r16) * 48 + koff;                         \
    const uint32_t boff = 2 * AT3 + (wn * 32 + r16) * 48 + koff;               \
    for (int t = 0; t < 64; t++) {                                             \
        CP_WAIT2();                                                            \
        __syncthreads();                                                       \
        const uint32_t s0 = sb + (t & 3) * STG3;                               \
        uint32_t bh[2][4], bl[2][4];                                           \
        _Pragma("unroll") for (int p = 0; p < 2; p++) {                        \
            const uint32_t bd = s0 + boff + p * 16 * 48;                       \
            ldsm4(bh[p], bd);                                                  \
            ldsm4(bl[p], bd + AT3);                                            \
        }                                                                      \
        _Pragma("unroll") for (int mt = 0; mt < 4; mt++) {                     \
            uint32_t ah[4], al[4];                                             \
            const uint32_t ad = s0 + aoff + mt * 16 * 48;                      \
            ldsm4(ah, ad);                                                     \
            ldsm4(al, ad + AT3);                                               \
            _Pragma("unroll") for (int nt = 0; nt < 4; nt++) {                 \
                const int p = nt >> 1, s = nt & 1;                             \
                mma_bf16(acc[mt][nt], ah, bh[p][s], bh[p][s + 2]);             \
                mma_bf16(acc[mt][nt], al, bh[p][s], bh[p][s + 2]);             \
                mma_bf16(acc[mt][nt], ah, bl[p][s], bl[p][s + 2]);             \
            }                                                                  \
        }                                                                      \
        if (t + 3 < 64) {                                                      \
            const uint32_t sa = sb + ((t + 3) & 3) * STG3 + swr;               \
            const int kb2 = (t + 3) * 32;                                      \
            cp16(sa,           gA_h + kb2);                                    \
            cp16(sa + AT3,     gA_l + kb2);                                    \
            cp16(sa + 2 * AT3, gB_h + kb2);                                    \
            cp16(sa + 3 * AT3, gB_l + kb2);                                    \
        }                                                                      \
        CP_COMMIT();                                                           \
    }

// Fused QKV GEMM: bn 0-7 -> Q (A=LH, W0, qb, scale 1/32), 8-15 -> K, 16-23 -> V
__global__ __launch_bounds__(256, 2) void gemm_qkv(
    const __nv_bfloat16* __restrict__ LHh, const __nv_bfloat16* __restrict__ LHl,
    const __nv_bfloat16* __restrict__ VHh, const __nv_bfloat16* __restrict__ VHl,
    const __nv_bfloat16* __restrict__ WH,  const __nv_bfloat16* __restrict__ WL,
    const float* __restrict__ qb, const float* __restrict__ kb,
    const float* __restrict__ vb,
    __nv_bfloat16* __restrict__ Qh, __nv_bfloat16* __restrict__ Ql,
    __nv_bfloat16* __restrict__ Kh, __nv_bfloat16* __restrict__ Kl,
    __nv_bfloat16* __restrict__ Vh, __nv_bfloat16* __restrict__ Vl)
{
    char* smg = dyn_smem;
    const uint32_t sb = smem_u32(smg);
    const int tid = threadIdx.x, lane = tid & 31, wid = tid >> 5;
    const int wm = wid >> 2, wn = wid & 3;
    const int bn = blockIdx.x, bm = blockIdx.y;
    const int sec = bn >> 3, bnl = bn & 7;

    const __nv_bfloat16* Ah_ = (sec == 0 ? LHh : VHh) + (size_t)bm * 128 * HID;
    const __nv_bfloat16* Al_ = (sec == 0 ? LHl : VHl) + (size_t)bm * 128 * HID;
    const __nv_bfloat16* Bh_ = WH + (size_t)sec * HID * HID + (size_t)bnl * 128 * HID;
    const __nv_bfloat16* Bl_ = WL + (size_t)sec * HID * HID + (size_t)bnl * 128 * HID;

    GEMM_CORE(Ah_, Al_, Bh_, Bl_)

    const float* bias = sec == 0 ? qb : sec == 1 ? kb : vb;
    const float scale = sec == 0 ? 0.03125f : 1.0f;
    __nv_bfloat16* Chi = sec == 0 ? Qh : sec == 1 ? Kh : Vh;
    __nv_bfloat16* Clo = sec == 0 ? Ql : sec == 1 ? Kl : Vl;

    #pragma unroll
    for (int mt = 0; mt < 4; mt++) {
        const size_t grow = (size_t)(bm * 128 + wm * 64 + mt * 16 + (lane >> 2));
        #pragma unroll
        for (int nt = 0; nt < 4; nt++) {
            const int col = bnl * 128 + wn * 32 + nt * 8 + (lane & 3) * 2;
            const float2 bb = *reinterpret_cast<const float2*>(bias + col);
            uint32_t lo0, lo1;
            const uint32_t hi0 =
                pack2((acc[mt][nt][0] + bb.x) * scale, (acc[mt][nt][1] + bb.y) * scale, lo0);
            const uint32_t hi1 =
                pack2((acc[mt][nt][2] + bb.x) * scale, (acc[mt][nt][3] + bb.y) * scale, lo1);
            *reinterpret_cast<uint32_t*>(Chi + grow * HID + col) = hi0;
            *reinterpret_cast<uint32_t*>(Clo + grow * HID + col) = lo0;
            *reinterpret_cast<uint32_t*>(Chi + (grow + 8) * HID + col) = hi1;
            *reinterpret_cast<uint32_t*>(Clo + (grow + 8) * HID + col) = lo1;
        }
    }
}

// O-projection GEMM: fp32 output
__global__ __launch_bounds__(256, 2) void gemm_out(
    const __nv_bfloat16* __restrict__ Ahp, const __nv_bfloat16* __restrict__ Alp,
    const __nv_bfloat16* __restrict__ Bhp, const __nv_bfloat16* __restrict__ Blp,
    const float* __restrict__ bias, float* __restrict__ Cf)
{
    char* smg = dyn_smem;
    const uint32_t sb = smem_u32(smg);
    const int tid = threadIdx.x, lane = tid & 31, wid = tid >> 5;
    const int wm = wid >> 2, wn = wid & 3;
    const int bn = blockIdx.x, bm = blockIdx.y;

    const __nv_bfloat16* Ah_ = Ahp + (size_t)bm * 128 * HID;
    const __nv_bfloat16* Al_ = Alp + (size_t)bm * 128 * HID;
    const __nv_bfloat16* Bh_ = Bhp + (size_t)bn * 128 * HID;
    const __nv_bfloat16* Bl_ = Blp + (size_t)bn * 128 * HID;

    GEMM_CORE(Ah_, Al_, Bh_, Bl_)

    #pragma unroll
    for (int mt = 0; mt < 4; mt++) {
        const size_t grow = (size_t)(bm * 128 + wm * 64 + mt * 16 + (lane >> 2));
        #pragma unroll
        for (int nt = 0; nt < 4; nt++) {
            const int col = bn * 128 + wn * 32 + nt * 8 + (lane & 3) * 2;
            const float2 bb = *reinterpret_cast<const float2*>(bias + col);
            float2 o0 = {acc[mt][nt][0] + bb.x, acc[mt][nt][1] + bb.y};
            float2 o1 = {acc[mt][nt][2] + bb.x, acc[mt][nt][3] + bb.y};
            *reinterpret_cast<float2*>(Cf + grow * HID + col) = o0;
            *reinterpret_cast<float2*>(Cf + (grow + 8) * HID + col) = o1;
        }
    }
}

// ---------------------------------------------------------------------------
// Flash attention (R14, passing) — now 3 CTAs/SM.
// ---------------------------------------------------------------------------
#define FR 144
#define FT 18432
#define F_SMEM (4 * FT)

__global__ __launch_bounds__(128, 3) void flash_mma(
    const __nv_bfloat16* __restrict__ Qh, const __nv_bfloat16* __restrict__ Ql,
    const __nv_bfloat16* __restrict__ Kh, const __nv_bfloat16* __restrict__ Kl,
    const __nv_bfloat16* __restrict__ Vh, const __nv_bfloat16* __restrict__ Vl,
    __nv_bfloat16* __restrict__ Ahi, __nv_bfloat16* __restrict__ Alo)
{
    char* smg = dyn_smem;
    const uint32_t sb = smem_u32(smg);
    const int tid = threadIdx.x, lane = tid & 31, wid = tid >> 5;
    const int qt = blockIdx.x, h = blockIdx.y, b = blockIdx.z;
    const size_t qbase = (size_t)(b * SEQ + qt * 64);
    const size_t kbase = (size_t)(b * SEQ);
    const int colh = h * HDIM;

    const int lr = tid >> 3;
    const int lseg = tid & 7;

    #pragma unroll
    for (int p = 0; p < 4; p++) {
        const int row = lr + p * 16;
        const uint32_t sa = sb + row * FR + lseg * 16;
        const size_t go = (qbase + row) * HID + colh;
        cp16(sa,      (const char*)(Qh + go) + lseg * 16);
        cp16(sa + FT, (const char*)(Ql + go) + lseg * 16);
    }
    CP_COMMIT();
    CP_WAIT0();
    __syncthreads();

    uint32_t qh[4][4], ql[4][4];
    {
        const uint32_t base = sb + (wid * 16 + (lane & 15)) * FR + (lane >> 4) * 16;
        #pragma unroll
        for (int ks = 0; ks < 4; ks++) {
            ldsm4(qh[ks], base + ks * 32);
            ldsm4(ql[ks], base + ks * 32 + FT);
        }
    }
    __syncthreads();

    float m0 = -1e30f, m1 = -1e30f, l0 = 0.0f, l1 = 0.0f;
    float oacc[8][4];
    #pragma unroll
    for (int j = 0; j < 8; j++)
        #pragma unroll
        for (int r = 0; r < 4; r++) oacc[j][r] = 0.0f;

    for (int kt = 0; kt < 8; kt++) {
        #pragma unroll
        for (int p = 0; p < 8; p++) {
            const int row = lr + p * 16;
            const uint32_t sa = sb + row * FR + lseg * 16;
            const size_t go = (kbase + (size_t)kt * 128 + row) * HID + colh;
            cp16(sa,      (const char*)(Kh + go) + lseg * 16);
            cp16(sa + FT, (const char*)(Kl + go) + lseg * 16);
        }
        CP_COMMIT();
        #pragma unroll
        for (int p = 0; p < 8; p++) {
            const int row = lr + p * 16;
            const uint32_t sa = sb + 2 * FT + row * FR + lseg * 16;
            const size_t go = (kbase + (size_t)kt * 128 + row) * HID + colh;
            cp16(sa,      (const char*)(Vh + go) + lseg * 16);
            cp16(sa + FT, (const char*)(Vl + go) + lseg * 16);
        }
        CP_COMMIT();

        CP_WAIT1();
        __syncthreads();

        float sacc[16][4];
        #pragma unroll
        for (int j = 0; j < 16; j++)
            #pragma unroll
            for (int r = 0; r < 4; r++) sacc[j][r] = 0.0f;

        #pragma unroll
        for (int ks = 0; ks < 4; ks++) {
            const uint32_t koff = ks * 32 + (lane >> 4) * 16;
            #pragma unroll
            for (int kg = 0; kg < 8; kg++) {
                uint32_t bh[4], bl[4];
                const uint32_t bd = sb + (kg * 16 + (lane & 15)) * FR + koff;
                ldsm4(bh, bd);
                ldsm4(bl, bd + FT);
                mma_bf16(sacc[2 * kg],     qh[ks], bh[0], bh[2]);
                mma_bf16(sacc[2 * kg],     ql[ks], bh[0], bh[2]);
                mma_bf16(sacc[2 * kg],     qh[ks], bl[0], bl[2]);
                mma_bf16(sacc[2 * kg + 1], qh[ks], bh[1], bh[3]);
                mma_bf16(sacc[2 * kg + 1], ql[ks], bh[1], bh[3]);
                mma_bf16(sacc[2 * kg + 1], qh[ks], bl[1], bl[3]);
            }
        }

        float tm0 = -1e30f, tm1 = -1e30f;
        #pragma unroll
        for (int j = 0; j < 16; j++) {
            tm0 = fmaxf(tm0, fmaxf(sacc[j][0], sacc[j][1]));
            tm1 = fmaxf(tm1, fmaxf(sacc[j][2], sacc[j][3]));
        }
        tm0 = fmaxf(tm0, __shfl_xor_sync(0xffffffffu, tm0, 1));
        tm0 = fmaxf(tm0, __shfl_xor_sync(0xffffffffu, tm0, 2));
        tm1 = fmaxf(tm1, __shfl_xor_sync(0xffffffffu, tm1, 1));
        tm1 = fmaxf(tm1, __shfl_xor_sync(0xffffffffu, tm1, 2));
        const float nm0 = fmaxf(m0, tm0), nm1 = fmaxf(m1, tm1);
        const float a0 = __expf(m0 - nm0), a1 = __expf(m1 - nm1);
        float rs0 = 0.0f, rs1 = 0.0f;
        #pragma unroll
        for (int j = 0; j < 16; j++) {
            sacc[j][0] = __expf(sacc[j][0] - nm0);
            sacc[j][1] = __expf(sacc[j][1] - nm0);
            sacc[j][2] = __expf(sacc[j][2] - nm1);
            sacc[j][3] = __expf(sacc[j][3] - nm1);
            rs0 += sacc[j][0] + sacc[j][1];
            rs1 += sacc[j][2] + sacc[j][3];
        }
        rs0 += __shfl_xor_sync(0xffffffffu, rs0, 1);
        rs0 += __shfl_xor_sync(0xffffffffu, rs0, 2);
        rs1 += __shfl_xor_sync(0xffffffffu, rs1, 1);
        rs1 += __shfl_xor_sync(0xffffffffu, rs1, 2);
        l0 = l0 * a0 + rs0;
        l1 = l1 * a1 + rs1;
        m0 = nm0; m1 = nm1;
        #pragma unroll
        for (int j = 0; j < 8; j++) {
            oacc[j][0] *= a0; oacc[j][1] *= a0;
            oacc[j][2] *= a1; oacc[j][3] *= a1;
        }

        CP_WAIT0();
        __syncthreads();

        #pragma unroll
        for (int ks = 0; ks < 8; ks++) {
            uint32_t ah[4], al[4];
            ah[0] = pack2(sacc[2 * ks][0],     sacc[2 * ks][1],     al[0]);
            ah[1] = pack2(sacc[2 * ks][2],     sacc[2 * ks][3],     al[1]);
            ah[2] = pack2(sacc[2 * ks + 1][0], sacc[2 * ks + 1][1], al[2]);
            ah[3] = pack2(sacc[2 * ks + 1][2], sacc[2 * ks + 1][3], al[3]);
            const uint32_t vbase =
                sb + 2 * FT + (ks * 16 + (lane & 15)) * FR + (lane >> 4) * 16;
            #pragma unroll
            for (int j = 0; j < 4; j++) {
                uint32_t vh[4], vl[4];
                ldsm4t(vh, vbase + j * 32);
                ldsm4t(vl, vbase + j * 32 + FT);
                mma_bf16(oacc[2 * j],     ah, vh[0], vh[1]);
                mma_bf16(oacc[2 * j],     al, vh[0], vh[1]);
                mma_bf16(oacc[2 * j],     ah, vl[0], vl[1]);
                mma_bf16(oacc[2 * j + 1], ah, vh[2], vh[3]);
                mma_bf16(oacc[2 * j + 1], al, vh[2], vh[3]);
                mma_bf16(oacc[2 * j + 1], ah, vl[2], vl[3]);
            }
        }
        __syncthreads();
    }

    const float il0 = 1.0f / l0, il1 = 1.0f / l1;
    const size_t row0 = qbase + wid * 16 + (lane >> 2);
    #pragma unroll
    for (int j = 0; j < 8; j++) {
        const int col = colh + j * 8 + (lane & 3) * 2;
        uint32_t lo0, lo1;
        const uint32_t hi0 = pack2(oacc[j][0] * il0, oacc[j][1] * il0, lo0);
        const uint32_t hi1 = pack2(oacc[j][2] * il1, oacc[j][3] * il1, lo1);
        *reinterpret_cast<uint32_t*>(Ahi + row0 * HID + col) = hi0;
        *reinterpret_cast<uint32_t*>(Alo + row0 * HID + col) = lo0;
        *reinterpret_cast<uint32_t*>(Ahi + (row0 + 8) * HID + col) = hi1;
        *reinterpret_cast<uint32_t*>(Alo + (row0 + 8) * HID + col) = lo1;
    }
}

// ---------------------------------------------------------------------------
extern "C" void kernel_launch(void* const* d_in, const int* in_sizes, int n_in,
                              void* d_out, int out_size)
{
    const float* vh = (const float*)d_in[0];
    const float* lh = (const float*)d_in[1];
    const float* qw = (const float*)d_in[2];
    const float* qb = (const float*)d_in[3];
    const float* kw = (const float*)d_in[4];
    const float* kb = (const float*)d_in[5];
    const float* vw = (const float*)d_in[6];
    const float* vb = (const float*)d_in[7];
    const float* ow = (const float*)d_in[8];
    const float* ob = (const float*)d_in[9];
    float* out = (float*)d_out;

    __nv_bfloat16 *WH, *WL, *LHh, *LHl, *VHh, *VHl;
    __nv_bfloat16 *Qh, *Ql, *Kh, *Kl, *Vh, *Vl, *Ah, *Al;
    cudaGetSymbolAddress((void**)&WH,  g_W_hi);
    cudaGetSymbolAddress((void**)&WL,  g_W_lo);
    cudaGetSymbolAddress((void**)&LHh, g_LHh);
    cudaGetSymbolAddress((void**)&LHl, g_LHl);
    cudaGetSymbolAddress((void**)&VHh, g_VHh);
    cudaGetSymbolAddress((void**)&VHl, g_VHl);
    cudaGetSymbolAddress((void**)&Qh,  g_Qh);
    cudaGetSymbolAddress((void**)&Ql,  g_Ql);
    cudaGetSymbolAddress((void**)&Kh,  g_Kh);
    cudaGetSymbolAddress((void**)&Kl,  g_Kl);
    cudaGetSymbolAddress((void**)&Vh,  g_Vh);
    cudaGetSymbolAddress((void**)&Vl,  g_Vl);
    cudaGetSymbolAddress((void**)&Ah,  g_Ah);
    cudaGetSymbolAddress((void**)&Al,  g_Al);
    const size_t WSZ = (size_t)HID * HID;

    wprep4<<<dim3(HID / 32, HID / 32, 4), dim3(32, 8)>>>(qw, kw, vw, ow, WH, WL);
    aprep<<<dim3(MTOT * HID / 1024, 1, 2), 256>>>(lh, vh, LHh, LHl, VHh, VHl);

    cudaFuncSetAttribute(gemm_qkv, cudaFuncAttributeMaxDynamicSharedMemorySize,
                         G3_SMEM);
    cudaFuncSetAttribute(gemm_out, cudaFuncAttributeMaxDynamicSharedMemorySize,
                         G3_SMEM);
    cudaFuncSetAttribute(flash_mma, cudaFuncAttributeMaxDynamicSharedMemorySize,
                         F_SMEM);

    // fused QKV: grid (24, 32) — bn 0-7 Q, 8-15 K, 16-23 V
    gemm_qkv<<<dim3(24, MTOT / 128), 256, G3_SMEM>>>(
        LHh, LHl, VHh, VHl, WH, WL, qb, kb, vb, Qh, Ql, Kh, Kl, Vh, Vl);

    flash_mma<<<dim3(SEQ / 64, NH, BATCH), 128, F_SMEM>>>(Qh, Ql, Kh, Kl,
                                                          Vh, Vl, Ah, Al);

    gemm_out<<<dim3(HID / 128, MTOT / 128), 256, G3_SMEM>>>(
        Ah, Al, WH + 3 * WSZ, WL + 3 * WSZ, ob, out);
}

// round 17
// speedup vs baseline: 1.0931x; 1.0188x over previous
#include <cuda_runtime.h>
#include <cuda_bf16.h>
#include <math.h>
#include <stdint.h>

#define BATCH 4
#define SEQ   1024
#define HID   1024
#define NH    16
#define HDIM  64
#define MTOT  (BATCH * SEQ)   // 4096

// ---------------------------------------------------------------------------
// Scratch (allocation-free rule: __device__ globals)
// ---------------------------------------------------------------------------
__device__ __nv_bfloat16 g_W_hi[4][HID * HID];
__device__ __nv_bfloat16 g_W_lo[4][HID * HID];
__device__ __nv_bfloat16 g_LHh[MTOT * HID], g_LHl[MTOT * HID];
__device__ __nv_bfloat16 g_VHh[MTOT * HID], g_VHl[MTOT * HID];
__device__ __nv_bfloat16 g_Qh[MTOT * HID],  g_Ql[MTOT * HID];
__device__ __nv_bfloat16 g_Kh[MTOT * HID],  g_Kl[MTOT * HID];
__device__ __nv_bfloat16 g_Vh[MTOT * HID],  g_Vl[MTOT * HID];
__device__ __nv_bfloat16 g_Ah[MTOT * HID],  g_Al[MTOT * HID];

// ---------------------------------------------------------------------------
// Helpers
// ---------------------------------------------------------------------------
__device__ __forceinline__ uint32_t smem_u32(const void* p) {
    return (uint32_t)__cvta_generic_to_shared(p);
}
__device__ __forceinline__ void ldsm4(uint32_t r[4], uint32_t addr) {
    asm volatile("ldmatrix.sync.aligned.m8n8.x4.shared.b16 {%0,%1,%2,%3}, [%4];"
                 : "=r"(r[0]), "=r"(r[1]), "=r"(r[2]), "=r"(r[3]) : "r"(addr));
}
__device__ __forceinline__ void ldsm4t(uint32_t r[4], uint32_t addr) {
    asm volatile("ldmatrix.sync.aligned.m8n8.x4.trans.shared.b16 {%0,%1,%2,%3}, [%4];"
                 : "=r"(r[0]), "=r"(r[1]), "=r"(r[2]), "=r"(r[3]) : "r"(addr));
}
__device__ __forceinline__ void mma_bf16(float c[4], const uint32_t a[4],
                                         uint32_t b0, uint32_t b1) {
    asm volatile(
        "mma.sync.aligned.m16n8k16.row.col.f32.bf16.bf16.f32 "
        "{%0,%1,%2,%3}, {%4,%5,%6,%7}, {%8,%9}, {%0,%1,%2,%3};"
        : "+f"(c[0]), "+f"(c[1]), "+f"(c[2]), "+f"(c[3])
        : "r"(a[0]), "r"(a[1]), "r"(a[2]), "r"(a[3]), "r"(b0), "r"(b1));
}
__device__ __forceinline__ void cp16(uint32_t s, const void* g) {
    asm volatile("cp.async.cg.shared.global [%0], [%1], 16;" :: "r"(s), "l"(g));
}
#define CP_COMMIT() asm volatile("cp.async.commit_group;")
#define CP_WAIT0()  asm volatile("cp.async.wait_group 0;")
#define CP_WAIT1()  asm volatile("cp.async.wait_group 1;")
#define CP_WAIT4()  asm volatile("cp.async.wait_group 4;")

__device__ __forceinline__ void split4(float4 x, uint2& hi, uint2& lo) {
    __nv_bfloat162 h0 = __floats2bfloat162_rn(x.x, x.y);
    __nv_bfloat162 h1 = __floats2bfloat162_rn(x.z, x.w);
    float2 f0 = __bfloat1622float2(h0);
    float2 f1 = __bfloat1622float2(h1);
    __nv_bfloat162 l0 = __floats2bfloat162_rn(x.x - f0.x, x.y - f0.y);
    __nv_bfloat162 l1 = __floats2bfloat162_rn(x.z - f1.x, x.w - f1.y);
    hi.x = *reinterpret_cast<uint32_t*>(&h0);
    hi.y = *reinterpret_cast<uint32_t*>(&h1);
    lo.x = *reinterpret_cast<uint32_t*>(&l0);
    lo.y = *reinterpret_cast<uint32_t*>(&l1);
}
__device__ __forceinline__ uint32_t pack2(float x, float y, uint32_t& lo) {
    __nv_bfloat162 h = __floats2bfloat162_rn(x, y);
    float2 f = __bfloat1622float2(h);
    __nv_bfloat162 l = __floats2bfloat162_rn(x - f.x, y - f.y);
    lo = *reinterpret_cast<uint32_t*>(&l);
    return *reinterpret_cast<uint32_t*>(&h);
}

extern __shared__ char dyn_smem[];

// ---------------------------------------------------------------------------
// Weight prep (fused): W[K,N] fp32 -> WT_hi/WT_lo [N,K] bf16, all 4 weights
// ---------------------------------------------------------------------------
__global__ __launch_bounds__(256) void wprep4(
    const float* __restrict__ Wq, const float* __restrict__ Wk,
    const float* __restrict__ Wv, const float* __restrict__ Wo,
    __nv_bfloat16* __restrict__ WH, __nv_bfloat16* __restrict__ WL)
{
    __shared__ float t[32][33];
    const int z = blockIdx.z;
    const float* W = (z == 0) ? Wq : (z == 1) ? Wk : (z == 2) ? Wv : Wo;
    __nv_bfloat16* WT_hi = WH + (size_t)z * HID * HID;
    __nv_bfloat16* WT_lo = WL + (size_t)z * HID * HID;
    const int tx = threadIdx.x, ty = threadIdx.y;
    const int nb = blockIdx.x * 32, kb = blockIdx.y * 32;
    #pragma unroll
    for (int r = 0; r < 4; r++)
        t[ty + r * 8][tx] = W[(size_t)(kb + ty + r * 8) * HID + nb + tx];
    __syncthreads();
    #pragma unroll
    for (int r = 0; r < 4; r++) {
        const int n = nb + ty + r * 8;
        const int k = kb + tx;
        const float x = t[tx][ty + r * 8];
        __nv_bfloat16 h = __float2bfloat16(x);
        WT_hi[(size_t)n * HID + k] = h;
        WT_lo[(size_t)n * HID + k] = __float2bfloat16(x - __bfloat162float(h));
    }
}

// ---------------------------------------------------------------------------
// Activation prep: fp32 X -> hi/lo bf16 (elementwise). grid.z picks input.
// ---------------------------------------------------------------------------
__global__ __launch_bounds__(256) void aprep(
    const float* __restrict__ X0, const float* __restrict__ X1,
    __nv_bfloat16* __restrict__ H0, __nv_bfloat16* __restrict__ L0,
    __nv_bfloat16* __restrict__ H1, __nv_bfloat16* __restrict__ L1)
{
    const float* X = blockIdx.z ? X1 : X0;
    __nv_bfloat16* H = blockIdx.z ? H1 : H0;
    __nv_bfloat16* L = blockIdx.z ? L1 : L0;
    const size_t i = ((size_t)blockIdx.x * 256 + threadIdx.x) * 4;
    float4 x = *reinterpret_cast<const float4*>(X + i);
    uint2 hi, lo;
    split4(x, hi, lo);
    *reinterpret_cast<uint2*>(H + i) = hi;
    *reinterpret_cast<uint2*>(L + i) = lo;
}

// ---------------------------------------------------------------------------
// bf16 GEMM: tile 128x128, BK=16, 6 cp.async stages (5 in flight),
// XOR-swizzled 32B rows (no pad, ldmatrix conflict-free), 2 CTAs/SM.
// smem stage: Ahi|Alo|Bhi|Blo each 128x32B = 4096 -> 16384/stage; x6 = 98304.
// ---------------------------------------------------------------------------
#define AT4   4096
#define STG4  16384
#define G4_SMEM (6 * STG4)   // 98304

#define GEMM_CORE(Ahg, Alg, Bhg, Blg)                                          \
    float acc[4][4][4];                                                        \
    _Pragma("unroll") for (int i = 0; i < 4; i++)                              \
        _Pragma("unroll") for (int j = 0; j < 4; j++)                          \
            _Pragma("unroll") for (int r = 0; r < 4; r++) acc[i][j][r] = 0.0f; \
    const int lrow = tid >> 1, lseg = tid & 1;                                 \
    const char* gA_h = (const char*)((Ahg) + (size_t)lrow * HID) + lseg * 16;  \
    const char* gA_l = (const char*)((Alg) + (size_t)lrow * HID) + lseg * 16;  \
    const char* gB_h = (const char*)((Bhg) + (size_t)lrow * HID) + lseg * 16;  \
    const char* gB_l = (const char*)((Blg) + (size_t)lrow * HID) + lseg * 16;  \
    const uint32_t swr = lrow * 32 + ((lseg ^ ((lrow >> 2) & 1)) * 16);        \
    _Pragma("unroll") for (int s = 0; s < 5; s++) {                            \
        const uint32_t sa = sb + s * STG4 + swr;                               \
        cp16(sa,           gA_h + s * 32);                                     \
        cp16(sa + AT4,     gA_l + s * 32);                                     \
        cp16(sa + 2 * AT4, gB_h + s * 32);                                     \
        cp16(sa + 3 * AT4, gB_l + s * 32);                                     \
        CP_COMMIT();                                                           \
    }                                                                          \
    const int r16 = lane & 15, hs = lane >> 4;                                 \
    const uint32_t segx = (uint32_t)((hs ^ ((r16 >> 2) & 1)) * 16);            \
    const uint32_t aoff = (wm * 64 + r16) * 32 + segx;                         \
    const uint32_t boff = 2 * AT4 + (wn * 32 + r16) * 32 + segx;               \
    for (int t = 0; t < 64; t++) {                                             \
        CP_WAIT4();                                                            \
        __syncthreads();                                                       \
        const uint32_t s0 = sb + (t % 6) * STG4;                               \
        uint32_t bh[2][4], bl[2][4];                                           \
        _Pragma("unroll") for (int p = 0; p < 2; p++) {                        \
            const uint32_t bd = s0 + boff + p * 512;                           \
            ldsm4(bh[p], bd);                                                  \
            ldsm4(bl[p], bd + AT4);                                            \
        }                                                                      \
        _Pragma("unroll") for (int mt = 0; mt < 4; mt++) {                     \
            uint32_t ah[4], al[4];                                             \
            const uint32_t ad = s0 + aoff + mt * 512;                          \
            ldsm4(ah, ad);                                                     \
            ldsm4(al, ad + AT4);                                               \
            _Pragma("unroll") for (int nt = 0; nt < 4; nt++) {                 \
                const int p = nt >> 1, s = nt & 1;                             \
                mma_bf16(acc[mt][nt], ah, bh[p][s], bh[p][s + 2]);             \
                mma_bf16(acc[mt][nt], al, bh[p][s], bh[p][s + 2]);             \
                mma_bf16(acc[mt][nt], ah, bl[p][s], bl[p][s + 2]);             \
            }                                                                  \
        }                                                                      \
        if (t + 5 < 64) {                                                      \
            const uint32_t sa = sb + ((t + 5) % 6) * STG4 + swr;               \
            const int kb2 = (t + 5) * 32;                                      \
            cp16(sa,           gA_h + kb2);                                    \
            cp16(sa + AT4,     gA_l + kb2);                                    \
            cp16(sa + 2 * AT4, gB_h + kb2);                                    \
            cp16(sa + 3 * AT4, gB_l + kb2);                                    \
        }                                                                      \
        CP_COMMIT();                                                           \
    }

// Fused QKV GEMM: bn 0-7 -> Q, 8-15 -> K, 16-23 -> V
__global__ __launch_bounds__(256, 2) void gemm_qkv(
    const __nv_bfloat16* __restrict__ LHh, const __nv_bfloat16* __restrict__ LHl,
    const __nv_bfloat16* __restrict__ VHh, const __nv_bfloat16* __restrict__ VHl,
    const __nv_bfloat16* __restrict__ WH,  const __nv_bfloat16* __restrict__ WL,
    const float* __restrict__ qb, const float* __restrict__ kb,
    const float* __restrict__ vb,
    __nv_bfloat16* __restrict__ Qh, __nv_bfloat16* __restrict__ Ql,
    __nv_bfloat16* __restrict__ Kh, __nv_bfloat16* __restrict__ Kl,
    __nv_bfloat16* __restrict__ Vh, __nv_bfloat16* __restrict__ Vl)
{
    char* smg = dyn_smem;
    const uint32_t sb = smem_u32(smg);
    const int tid = threadIdx.x, lane = tid & 31, wid = tid >> 5;
    const int wm = wid >> 2, wn = wid & 3;
    const int bn = blockIdx.x, bm = blockIdx.y;
    const int sec = bn >> 3, bnl = bn & 7;

    const __nv_bfloat16* Ah_ = (sec == 0 ? LHh : VHh) + (size_t)bm * 128 * HID;
    const __nv_bfloat16* Al_ = (sec == 0 ? LHl : VHl) + (size_t)bm * 128 * HID;
    const __nv_bfloat16* Bh_ = WH + (size_t)sec * HID * HID + (size_t)bnl * 128 * HID;
    const __nv_bfloat16* Bl_ = WL + (size_t)sec * HID * HID + (size_t)bnl * 128 * HID;

    GEMM_CORE(Ah_, Al_, Bh_, Bl_)

    const float* bias = sec == 0 ? qb : sec == 1 ? kb : vb;
    const float scale = sec == 0 ? 0.03125f : 1.0f;
    __nv_bfloat16* Chi = sec == 0 ? Qh : sec == 1 ? Kh : Vh;
    __nv_bfloat16* Clo = sec == 0 ? Ql : sec == 1 ? Kl : Vl;

    #pragma unroll
    for (int mt = 0; mt < 4; mt++) {
        const size_t grow = (size_t)(bm * 128 + wm * 64 + mt * 16 + (lane >> 2));
        #pragma unroll
        for (int nt = 0; nt < 4; nt++) {
            const int col = bnl * 128 + wn * 32 + nt * 8 + (lane & 3) * 2;
            const float2 bb = *reinterpret_cast<const float2*>(bias + col);
            uint32_t lo0, lo1;
            const uint32_t hi0 =
                pack2((acc[mt][nt][0] + bb.x) * scale, (acc[mt][nt][1] + bb.y) * scale, lo0);
            const uint32_t hi1 =
                pack2((acc[mt][nt][2] + bb.x) * scale, (acc[mt][nt][3] + bb.y) * scale, lo1);
            *reinterpret_cast<uint32_t*>(Chi + grow * HID + col) = hi0;
            *reinterpret_cast<uint32_t*>(Clo + grow * HID + col) = lo0;
            *reinterpret_cast<uint32_t*>(Chi + (grow + 8) * HID + col) = hi1;
            *reinterpret_cast<uint32_t*>(Clo + (grow + 8) * HID + col) = lo1;
        }
    }
}

// O-projection GEMM: fp32 output
__global__ __launch_bounds__(256, 2) void gemm_out(
    const __nv_bfloat16* __restrict__ Ahp, const __nv_bfloat16* __restrict__ Alp,
    const __nv_bfloat16* __restrict__ Bhp, const __nv_bfloat16* __restrict__ Blp,
    const float* __restrict__ bias, float* __restrict__ Cf)
{
    char* smg = dyn_smem;
    const uint32_t sb = smem_u32(smg);
    const int tid = threadIdx.x, lane = tid & 31, wid = tid >> 5;
    const int wm = wid >> 2, wn = wid & 3;
    const int bn = blockIdx.x, bm = blockIdx.y;

    const __nv_bfloat16* Ah_ = Ahp + (size_t)bm * 128 * HID;
    const __nv_bfloat16* Al_ = Alp + (size_t)bm * 128 * HID;
    const __nv_bfloat16* Bh_ = Bhp + (size_t)bn * 128 * HID;
    const __nv_bfloat16* Bl_ = Blp + (size_t)bn * 128 * HID;

    GEMM_CORE(Ah_, Al_, Bh_, Bl_)

    #pragma unroll
    for (int mt = 0; mt < 4; mt++) {
        const size_t grow = (size_t)(bm * 128 + wm * 64 + mt * 16 + (lane >> 2));
        #pragma unroll
        for (int nt = 0; nt < 4; nt++) {
            const int col = bn * 128 + wn * 32 + nt * 8 + (lane & 3) * 2;
            const float2 bb = *reinterpret_cast<const float2*>(bias + col);
            float2 o0 = {acc[mt][nt][0] + bb.x, acc[mt][nt][1] + bb.y};
            float2 o1 = {acc[mt][nt][2] + bb.x, acc[mt][nt][3] + bb.y};
            *reinterpret_cast<float2*>(Cf + grow * HID + col) = o0;
            *reinterpret_cast<float2*>(Cf + (grow + 8) * HID + col) = o1;
        }
    }
}

// ---------------------------------------------------------------------------
// Flash attention: SW128-swizzled 128B rows (no pad), cross-iteration
// K/V prefetch overlap. smem: Khi|Klo|Vhi|Vlo, each 16384 -> 65536 (3 CTAs/SM)
// ---------------------------------------------------------------------------
#define FT2 16384
#define F2_SMEM (4 * FT2)

__global__ __launch_bounds__(128, 3) void flash_mma(
    const __nv_bfloat16* __restrict__ Qh, const __nv_bfloat16* __restrict__ Ql,
    const __nv_bfloat16* __restrict__ Kh, const __nv_bfloat16* __restrict__ Kl,
    const __nv_bfloat16* __restrict__ Vh, const __nv_bfloat16* __restrict__ Vl,
    __nv_bfloat16* __restrict__ Ahi, __nv_bfloat16* __restrict__ Alo)
{
    char* smg = dyn_smem;
    const uint32_t sb = smem_u32(smg);
    const int tid = threadIdx.x, lane = tid & 31, wid = tid >> 5;
    const int qt = blockIdx.x, h = blockIdx.y, b = blockIdx.z;
    const size_t qbase = (size_t)(b * SEQ + qt * 64);
    const size_t kbase = (size_t)(b * SEQ);
    const int colh = h * HDIM;

    const int lr = tid >> 3;        // row group 0..15
    const int lseg = tid & 7;       // 16B seg in 128B row
    const uint32_t wro = lr * 128 + ((lseg ^ (lr & 7)) * 16);  // swizzled write

    const int r16f = lane & 15, hsv = lane >> 4, l7 = lane & 7;

    // ---- prologue: Q hi/lo (64x64) into K region ----
    #pragma unroll
    for (int p = 0; p < 4; p++) {
        const uint32_t sa = sb + wro + p * 2048;
        const size_t go = (qbase + lr + p * 16) * HID + colh;
        cp16(sa,       (const char*)(Qh + go) + lseg * 16);
        cp16(sa + FT2, (const char*)(Ql + go) + lseg * 16);
    }
    CP_COMMIT();
    CP_WAIT0();
    __syncthreads();

    uint32_t qh[4][4], ql[4][4];
    {
        const uint32_t rowb = (wid * 16 + r16f) * 128;
        #pragma unroll
        for (int ks = 0; ks < 4; ks++) {
            const uint32_t ad = sb + rowb + (((ks * 2 + hsv) ^ l7) * 16);
            ldsm4(qh[ks], ad);
            ldsm4(ql[ks], ad + FT2);
        }
    }
    __syncthreads();

    // ---- K0, V0 ----
    #pragma unroll
    for (int p = 0; p < 8; p++) {
        const uint32_t sa = sb + wro + p * 2048;
        const size_t go = (kbase + lr + p * 16) * HID + colh;
        cp16(sa,       (const char*)(Kh + go) + lseg * 16);
        cp16(sa + FT2, (const char*)(Kl + go) + lseg * 16);
    }
    CP_COMMIT();
    #pragma unroll
    for (int p = 0; p < 8; p++) {
        const uint32_t sa = sb + 2 * FT2 + wro + p * 2048;
        const size_t go = (kbase + lr + p * 16) * HID + colh;
        cp16(sa,       (const char*)(Vh + go) + lseg * 16);
        cp16(sa + FT2, (const char*)(Vl + go) + lseg * 16);
    }
    CP_COMMIT();

    float m0 = -1e30f, m1 = -1e30f, l0 = 0.0f, l1 = 0.0f;
    float oacc[8][4];
    #pragma unroll
    for (int j = 0; j < 8; j++)
        #pragma unroll
        for (int r = 0; r < 4; r++) oacc[j][r] = 0.0f;

    for (int kt = 0; kt < 8; kt++) {
        CP_WAIT1();          // K_kt ready (V_kt may be in flight)
        __syncthreads();

        // ---- S = Q K^T ----
        float sacc[16][4];
        #pragma unroll
        for (int j = 0; j < 16; j++)
            #pragma unroll
            for (int r = 0; r < 4; r++) sacc[j][r] = 0.0f;

        #pragma unroll
        for (int ks = 0; ks < 4; ks++) {
            const uint32_t sgo = ((ks * 2 + hsv) ^ l7) * 16;
            #pragma unroll
            for (int kg = 0; kg < 8; kg++) {
                uint32_t bh[4], bl[4];
                const uint32_t bd = sb + (kg * 16 + r16f) * 128 + sgo;
                ldsm4(bh, bd);
                ldsm4(bl, bd + FT2);
                mma_bf16(sacc[2 * kg],     qh[ks], bh[0], bh[2]);
                mma_bf16(sacc[2 * kg],     ql[ks], bh[0], bh[2]);
                mma_bf16(sacc[2 * kg],     qh[ks], bl[0], bl[2]);
                mma_bf16(sacc[2 * kg + 1], qh[ks], bh[1], bh[3]);
                mma_bf16(sacc[2 * kg + 1], ql[ks], bh[1], bh[3]);
                mma_bf16(sacc[2 * kg + 1], qh[ks], bl[1], bl[3]);
            }
        }
        __syncthreads();     // all warps done reading K

        // ---- prefetch K(kt+1) — hidden behind softmax + PV ----
        if (kt < 7) {
            #pragma unroll
            for (int p = 0; p < 8; p++) {
                const uint32_t sa = sb + wro + p * 2048;
                const size_t go = (kbase + (size_t)(kt + 1) * 128 + lr + p * 16) * HID + colh;
                cp16(sa,       (const char*)(Kh + go) + lseg * 16);
                cp16(sa + FT2, (const char*)(Kl + go) + lseg * 16);
            }
        }
        CP_COMMIT();

        // ---- online softmax ----
        float tm0 = -1e30f, tm1 = -1e30f;
        #pragma unroll
        for (int j = 0; j < 16; j++) {
            tm0 = fmaxf(tm0, fmaxf(sacc[j][0], sacc[j][1]));
            tm1 = fmaxf(tm1, fmaxf(sacc[j][2], sacc[j][3]));
        }
        tm0 = fmaxf(tm0, __shfl_xor_sync(0xffffffffu, tm0, 1));
        tm0 = fmaxf(tm0, __shfl_xor_sync(0xffffffffu, tm0, 2));
        tm1 = fmaxf(tm1, __shfl_xor_sync(0xffffffffu, tm1, 1));
        tm1 = fmaxf(tm1, __shfl_xor_sync(0xffffffffu, tm1, 2));
        const float nm0 = fmaxf(m0, tm0), nm1 = fmaxf(m1, tm1);
        const float a0 = __expf(m0 - nm0), a1 = __expf(m1 - nm1);
        float rs0 = 0.0f, rs1 = 0.0f;
        #pragma unroll
        for (int j = 0; j < 16; j++) {
            sacc[j][0] = __expf(sacc[j][0] - nm0);
            sacc[j][1] = __expf(sacc[j][1] - nm0);
            sacc[j][2] = __expf(sacc[j][2] - nm1);
            sacc[j][3] = __expf(sacc[j][3] - nm1);
            rs0 += sacc[j][0] + sacc[j][1];
            rs1 += sacc[j][2] + sacc[j][3];
        }
        rs0 += __shfl_xor_sync(0xffffffffu, rs0, 1);
        rs0 += __shfl_xor_sync(0xffffffffu, rs0, 2);
        rs1 += __shfl_xor_sync(0xffffffffu, rs1, 1);
        rs1 += __shfl_xor_sync(0xffffffffu, rs1, 2);
        l0 = l0 * a0 + rs0;
        l1 = l1 * a1 + rs1;
        m0 = nm0; m1 = nm1;
        #pragma unroll
        for (int j = 0; j < 8; j++) {
            oacc[j][0] *= a0; oacc[j][1] *= a0;
            oacc[j][2] *= a1; oacc[j][3] *= a1;
        }

        CP_WAIT1();          // V_kt ready (K_{kt+1} may be in flight)
        __syncthreads();

        // ---- O += P V ----
        #pragma unroll
        for (int ks = 0; ks < 8; ks++) {
            uint32_t ah[4], al[4];
            ah[0] = pack2(sacc[2 * ks][0],     sacc[2 * ks][1],     al[0]);
            ah[1] = pack2(sacc[2 * ks][2],     sacc[2 * ks][3],     al[1]);
            ah[2] = pack2(sacc[2 * ks + 1][0], sacc[2 * ks + 1][1], al[2]);
            ah[3] = pack2(sacc[2 * ks + 1][2], sacc[2 * ks + 1][3], al[3]);
            const uint32_t vrow = sb + 2 * FT2 + (ks * 16 + r16f) * 128;
            #pragma unroll
            for (int j = 0; j < 4; j++) {
                uint32_t vh[4], vl[4];
                const uint32_t vd = vrow + (((j * 2 + hsv) ^ l7) * 16);
                ldsm4t(vh, vd);
                ldsm4t(vl, vd + FT2);
                mma_bf16(oacc[2 * j],     ah, vh[0], vh[1]);
                mma_bf16(oacc[2 * j],     al, vh[0], vh[1]);
                mma_bf16(oacc[2 * j],     ah, vl[0], vl[1]);
                mma_bf16(oacc[2 * j + 1], ah, vh[2], vh[3]);
                mma_bf16(oacc[2 * j + 1], al, vh[2], vh[3]);
                mma_bf16(oacc[2 * j + 1], ah, vl[2], vl[3]);
            }
        }
        __syncthreads();     // all warps done reading V

        // ---- prefetch V(kt+1) — hidden behind next S ----
        if (kt < 7) {
            #pragma unroll
            for (int p = 0; p < 8; p++) {
                const uint32_t sa = sb + 2 * FT2 + wro + p * 2048;
                const size_t go = (kbase + (size_t)(kt + 1) * 128 + lr + p * 16) * HID + colh;
                cp16(sa,       (const char*)(Vh + go) + lseg * 16);
                cp16(sa + FT2, (const char*)(Vl + go) + lseg * 16);
            }
        }
        CP_COMMIT();
    }

    const float il0 = 1.0f / l0, il1 = 1.0f / l1;
    const size_t row0 = qbase + wid * 16 + (lane >> 2);
    #pragma unroll
    for (int j = 0; j < 8; j++) {
        const int col = colh + j * 8 + (lane & 3) * 2;
        uint32_t lo0, lo1;
        const uint32_t hi0 = pack2(oacc[j][0] * il0, oacc[j][1] * il0, lo0);
        const uint32_t hi1 = pack2(oacc[j][2] * il1, oacc[j][3] * il1, lo1);
        *reinterpret_cast<uint32_t*>(Ahi + row0 * HID + col) = hi0;
        *reinterpret_cast<uint32_t*>(Alo + row0 * HID + col) = lo0;
        *reinterpret_cast<uint32_t*>(Ahi + (row0 + 8) * HID + col) = hi1;
        *reinterpret_cast<uint32_t*>(Alo + (row0 + 8) * HID + col) = lo1;
    }
}

// ---------------------------------------------------------------------------
extern "C" void kernel_launch(void* const* d_in, const int* in_sizes, int n_in,
                              void* d_out, int out_size)
{
    const float* vh = (const float*)d_in[0];
    const float* lh = (const float*)d_in[1];
    const float* qw = (const float*)d_in[2];
    const float* qb = (const float*)d_in[3];
    const float* kw = (const float*)d_in[4];
    const float* kb = (const float*)d_in[5];
    const float* vw = (const float*)d_in[6];
    const float* vb = (const float*)d_in[7];
    const float* ow = (const float*)d_in[8];
    const float* ob = (const float*)d_in[9];
    float* out = (float*)d_out;

    __nv_bfloat16 *WH, *WL, *LHh, *LHl, *VHh, *VHl;
    __nv_bfloat16 *Qh, *Ql, *Kh, *Kl, *Vh, *Vl, *Ah, *Al;
    cudaGetSymbolAddress((void**)&WH,  g_W_hi);
    cudaGetSymbolAddress((void**)&WL,  g_W_lo);
    cudaGetSymbolAddress((void**)&LHh, g_LHh);
    cudaGetSymbolAddress((void**)&LHl, g_LHl);
    cudaGetSymbolAddress((void**)&VHh, g_VHh);
    cudaGetSymbolAddress((void**)&VHl, g_VHl);
    cudaGetSymbolAddress((void**)&Qh,  g_Qh);
    cudaGetSymbolAddress((void**)&Ql,  g_Ql);
    cudaGetSymbolAddress((void**)&Kh,  g_Kh);
    cudaGetSymbolAddress((void**)&Kl,  g_Kl);
    cudaGetSymbolAddress((void**)&Vh,  g_Vh);
    cudaGetSymbolAddress((void**)&Vl,  g_Vl);
    cudaGetSymbolAddress((void**)&Ah,  g_Ah);
    cudaGetSymbolAddress((void**)&Al,  g_Al);
    const size_t WSZ = (size_t)HID * HID;

    wprep4<<<dim3(HID / 32, HID / 32, 4), dim3(32, 8)>>>(qw, kw, vw, ow, WH, WL);
    aprep<<<dim3(MTOT * HID / 1024, 1, 2), 256>>>(lh, vh, LHh, LHl, VHh, VHl);

    cudaFuncSetAttribute(gemm_qkv, cudaFuncAttributeMaxDynamicSharedMemorySize,
                         G4_SMEM);
    cudaFuncSetAttribute(gemm_out, cudaFuncAttributeMaxDynamicSharedMemorySize,
                         G4_SMEM);
    cudaFuncSetAttribute(flash_mma, cudaFuncAttributeMaxDynamicSharedMemorySize,
                         F2_SMEM);

    gemm_qkv<<<dim3(24, MTOT / 128), 256, G4_SMEM>>>(
        LHh, LHl, VHh, VHl, WH, WL, qb, kb, vb, Qh, Ql, Kh, Kl, Vh, Vl);

    flash_mma<<<dim3(SEQ / 64, NH, BATCH), 128, F2_SMEM>>>(Qh, Ql, Kh, Kl,
                                                           Vh, Vl, Ah, Al);

    gemm_out<<<dim3(HID / 128, MTOT / 128), 256, G4_SMEM>>>(
        Ah, Al, WH + 3 * WSZ, WL + 3 * WSZ, ob, out);
}